// round 10
// baseline (speedup 1.0000x reference)
#include <cuda_runtime.h>
#include <cstdint>

// Problem constants
#define B_    8
#define C_    512
#define N_    1024
#define HEADS 8
#define DH    64
#define GROUPS 32

// Scratch (allocation-free: device globals). All bf16 pair-packed as u32 words.
__device__ uint32_t g_h[(size_t)B_ * 256 * 1024];     // GN out, word(c2,n)   (8 MB)
__device__ uint32_t g_qkvw[(size_t)B_ * 1536 * 512];  // qkv bf16 [row][n/2]  (25 MB)
__device__ uint32_t g_aow[(size_t)B_ * 256 * 1024];   // attn out word(c2,n)  (8 MB)
__device__ uint32_t g_wq[1536 * 256];                 // qkv_w bf16
__device__ uint32_t g_wp[512 * 256];                  // proj_w bf16

// ---------------------------------------------------------------------------
// helpers (plain sm_80+ PTX — safe for the sm_103 compile target)
// ---------------------------------------------------------------------------
__device__ __forceinline__ void mma_bf16(float* c, const uint32_t* a, const uint32_t* b) {
    asm("mma.sync.aligned.m16n8k16.row.col.f32.bf16.bf16.f32 "
        "{%0,%1,%2,%3}, {%4,%5,%6,%7}, {%8,%9}, {%0,%1,%2,%3};"
        : "+f"(c[0]), "+f"(c[1]), "+f"(c[2]), "+f"(c[3])
        : "r"(a[0]), "r"(a[1]), "r"(a[2]), "r"(a[3]), "r"(b[0]), "r"(b[1]));
}
__device__ __forceinline__ void ldsm4(uint32_t* r, uint32_t addr) {
    asm volatile("ldmatrix.sync.aligned.m8n8.x4.shared.b16 {%0,%1,%2,%3}, [%4];"
                 : "=r"(r[0]), "=r"(r[1]), "=r"(r[2]), "=r"(r[3]) : "r"(addr));
}
__device__ __forceinline__ uint32_t bf2(float lo, float hi) {   // word: lo16=lo
    uint32_t w;
    asm("cvt.rn.satfinite.bf16x2.f32 %0, %1, %2;" : "=r"(w) : "f"(hi), "f"(lo));
    return w;
}
__device__ __forceinline__ uint32_t prmt(uint32_t a, uint32_t b, uint32_t s) {
    uint32_t d;
    asm("prmt.b32 %0, %1, %2, %3;" : "=r"(d) : "r"(a), "r"(b), "r"(s));
    return d;
}
__device__ __forceinline__ float ex2(float x) {
    float r;
    asm("ex2.approx.f32 %0, %1;" : "=f"(r) : "f"(x));
    return r;
}
__device__ __forceinline__ uint32_t smem_u32(const void* p) {
    uint32_t a;
    asm("{ .reg .u64 t; cvta.to.shared.u64 t, %1; cvt.u32.u64 %0, t; }"
        : "=r"(a) : "l"(p));
    return a;
}
__device__ __forceinline__ void cp16(uint32_t dst, const void* src) {
    asm volatile("cp.async.cg.shared.global [%0], [%1], 16;" :: "r"(dst), "l"(src));
}
#define CP_COMMIT() asm volatile("cp.async.commit_group;" ::: "memory")
#define CP_WAIT(n)  asm volatile("cp.async.wait_group %0;" :: "n"(n) : "memory")

// ---------------------------------------------------------------------------
// Weight conversion: fp32 row-major -> bf16 pair words (same layout)
// ---------------------------------------------------------------------------
__global__ __launch_bounds__(256)
void wconv(const float4* __restrict__ src, uint2* __restrict__ dst, int n4) {
    int i = blockIdx.x * 256 + threadIdx.x;
    if (i < n4) {
        float4 v = src[i];
        dst[i] = make_uint2(bf2(v.x, v.y), bf2(v.z, v.w));
    }
}

// ---------------------------------------------------------------------------
// GroupNorm -> bf16 word(c2, n) = (h[2c2,n], h[2c2+1,n])
// ---------------------------------------------------------------------------
__global__ __launch_bounds__(256)
void gn_kernel(const float* __restrict__ x, const float* __restrict__ w,
               const float* __restrict__ bb) {
    int bg = blockIdx.x;
    int b = bg >> 5, g = bg & 31;
    const float4* xp = (const float4*)(x + ((size_t)b * C_ + g * 16) * N_);

    float s = 0.f, s2 = 0.f;
    for (int idx = threadIdx.x; idx < 4096; idx += 256) {
        float4 v = xp[idx];
        s  += v.x + v.y + v.z + v.w;
        s2 += v.x * v.x + v.y * v.y + v.z * v.z + v.w * v.w;
    }
    #pragma unroll
    for (int off = 16; off; off >>= 1) {
        s  += __shfl_xor_sync(0xffffffffu, s, off);
        s2 += __shfl_xor_sync(0xffffffffu, s2, off);
    }
    __shared__ float sh[16];
    __shared__ float smu, srstd;
    int warp = threadIdx.x >> 5, lane = threadIdx.x & 31;
    if (lane == 0) { sh[warp] = s; sh[warp + 8] = s2; }
    __syncthreads();
    if (threadIdx.x == 0) {
        float ts = 0.f, ts2 = 0.f;
        #pragma unroll
        for (int i = 0; i < 8; i++) { ts += sh[i]; ts2 += sh[i + 8]; }
        float mu  = ts * (1.f / 16384.f);
        float var = ts2 * (1.f / 16384.f) - mu * mu;
        smu = mu;
        srstd = rsqrtf(var + 1e-5f);
    }
    __syncthreads();
    float mu = smu, rstd = srstd;

    uint32_t* hw = g_h + ((size_t)(b * 256 + g * 8)) * 1024;
    int tid = threadIdx.x;
    #pragma unroll
    for (int cc = 0; cc < 8; cc++) {
        int c = g * 16 + cc * 2;
        float s0 = w[c] * rstd,     t0 = bb[c]     - mu * s0;
        float s1 = w[c + 1] * rstd, t1 = bb[c + 1] - mu * s1;
        const float4* xa = (const float4*)(x + ((size_t)b * C_ + c) * N_);
        float4 va = xa[tid], vb = xa[256 + tid];
        uint4 wv;
        wv.x = bf2(va.x * s0 + t0, vb.x * s1 + t1);
        wv.y = bf2(va.y * s0 + t0, vb.y * s1 + t1);
        wv.z = bf2(va.z * s0 + t0, vb.z * s1 + t1);
        wv.w = bf2(va.w * s0 + t0, vb.w * s1 + t1);
        *(uint4*)(hw + cc * 1024 + tid * 4) = wv;
    }
}

// ---------------------------------------------------------------------------
// bf16 mma.sync GEMM: 3-stage cp.async pipeline, one barrier per K-tile,
// ldmatrix A-fragments. CTA 128x128, 8 warps (2x4), warp tile 64x32.
// ---------------------------------------------------------------------------
#define PA 20
#define PB 136
#define STG_W (128 * PA + 16 * PB)            // 4736 words per stage
#define GM_SMEM (3 * STG_W * 4)               // 56,832 B

template <bool RES>
__global__ __launch_bounds__(256)
void tc_gemm(const uint32_t* __restrict__ A, const float* __restrict__ bias,
             const uint32_t* __restrict__ Bw, const float* __restrict__ X,
             float* __restrict__ OutF, uint32_t* __restrict__ OutW, int M) {
    extern __shared__ uint32_t smp[];

    int tid = threadIdx.x;
    int wid = tid >> 5, lane = tid & 31;
    int g = lane >> 2, tg = lane & 3;
    int warpM = wid >> 2, warpN = wid & 3;
    int wmRow = warpM * 64, wnCol = warpN * 32;

    // ldmatrix x4 source coords: matid 0..3 -> (row block, kpair block)
    int matid = lane >> 3, rowin = lane & 7;
    int lmRow = wmRow + (matid & 1) * 8 + rowin;
    int lmKp  = (matid >> 1) * 4;

    int b = blockIdx.z;
    int n0 = blockIdx.x * 128, o0 = blockIdx.y * 128;
    const uint32_t* Bp = Bw + (size_t)b * 256 * 1024;

    uint32_t sbase = smem_u32(smp);

    auto load_tile = [&](int t, int s) {
        uint32_t as = sbase + (uint32_t)(s * STG_W) * 4u;
        uint32_t bs = as + 128u * PA * 4u;
        #pragma unroll
        for (int it = 0; it < 2; it++) {
            int idx = it * 256 + tid;
            int o = idx >> 2, ch = idx & 3;
            cp16(as + (uint32_t)(o * PA + ch * 4) * 4u,
                 A + (size_t)(o0 + o) * 256 + t * 16 + ch * 4);
        }
        #pragma unroll
        for (int it = 0; it < 2; it++) {
            int idx = it * 256 + tid;
            int r = idx >> 5, ch = idx & 31;
            cp16(bs + (uint32_t)(r * PB + ch * 4) * 4u,
                 Bp + (size_t)(t * 16 + r) * 1024 + n0 + ch * 4);
        }
        CP_COMMIT();
    };

    float acc[4][4][4];
    #pragma unroll
    for (int mf = 0; mf < 4; mf++)
        #pragma unroll
        for (int nf = 0; nf < 4; nf++)
            #pragma unroll
            for (int i = 0; i < 4; i++) acc[mf][nf][i] = 0.f;

    load_tile(0, 0);
    load_tile(1, 1);

    for (int t = 0; t < 16; t++) {
        if (t < 15) { CP_WAIT(1); } else { CP_WAIT(0); }
        __syncthreads();              // tile t visible; stage (t+2)%3 free
        if (t + 2 < 16) load_tile(t + 2, (t + 2) % 3);

        int s = t % 3;
        const uint32_t* Bs = smp + s * STG_W + 128 * PA;
        uint32_t aAddr = sbase + (uint32_t)(s * STG_W + lmRow * PA + lmKp) * 4u;

        #pragma unroll
        for (int ks = 0; ks < 2; ks++) {
            uint32_t a[4][4], bfr[4][2];
            #pragma unroll
            for (int mf = 0; mf < 4; mf++)
                ldsm4(a[mf], aAddr + (uint32_t)(mf * 16 * PA + ks * 8) * 4u);
            #pragma unroll
            for (int nf = 0; nf < 4; nf++) {
                int col = wnCol + nf * 8 + g;
                bfr[nf][0] = Bs[(ks * 8 + tg) * PB + col];
                bfr[nf][1] = Bs[(ks * 8 + tg + 4) * PB + col];
            }
            #pragma unroll
            for (int mf = 0; mf < 4; mf++)
                #pragma unroll
                for (int nf = 0; nf < 4; nf++)
                    mma_bf16(acc[mf][nf], a[mf], bfr[nf]);
        }
    }

    #pragma unroll
    for (int mf = 0; mf < 4; mf++) {
        int r = o0 + wmRow + mf * 16 + g;
        float bi0 = bias[r], bi1 = bias[r + 8];
        if (RES) {
            size_t base0 = (size_t)b * M * N_ + (size_t)r * N_ + n0;
            size_t base1 = base0 + 8 * (size_t)N_;
            #pragma unroll
            for (int nf = 0; nf < 4; nf++) {
                int col = wnCol + nf * 8 + tg * 2;
                float2 v0 = make_float2(acc[mf][nf][0] + bi0, acc[mf][nf][1] + bi0);
                float2 v1 = make_float2(acc[mf][nf][2] + bi1, acc[mf][nf][3] + bi1);
                float2 x0 = *(const float2*)(X + base0 + col);
                float2 x1 = *(const float2*)(X + base1 + col);
                v0.x += x0.x; v0.y += x0.y;
                v1.x += x1.x; v1.y += x1.y;
                *(float2*)(OutF + base0 + col) = v0;
                *(float2*)(OutF + base1 + col) = v1;
            }
        } else {
            size_t w0 = ((size_t)b * 1536 + r) * 512;
            size_t w1 = w0 + 8 * 512;
            #pragma unroll
            for (int nf = 0; nf < 4; nf++) {
                int wc = ((n0 + wnCol + nf * 8) >> 1) + tg;
                OutW[w0 + wc] = bf2(acc[mf][nf][0] + bi0, acc[mf][nf][1] + bi0);
                OutW[w1 + wc] = bf2(acc[mf][nf][2] + bi1, acc[mf][nf][3] + bi1);
            }
        }
    }
}

// ---------------------------------------------------------------------------
// bf16 mma.sync flash attention (ex2.approx softmax).
// CTA = (b,h) x 128-query tile, 8 warps, warp tile 16(i) x 128(j).
// ---------------------------------------------------------------------------
#define PQ 136
#define PV 72
#define PP 68
#define QS_OFF 0
#define KS_OFF (32 * PQ)
#define VS_OFF (2 * 32 * PQ)
#define PS_OFF (2 * 32 * PQ + 64 * PV)
#define ATT_SMEM ((PS_OFF + 128 * PP) * 4)    // 88,064 B
#define K8 0.18033688011112042f               // 0.125 * log2(e)

__global__ __launch_bounds__(256, 2)
void attn_tc(const uint32_t* __restrict__ qkvw, uint32_t* __restrict__ aow) {
    extern __shared__ uint32_t smw[];
    uint32_t* Qs = smw + QS_OFF;
    uint32_t* Ks = smw + KS_OFF;
    uint32_t* Vs = smw + VS_OFF;
    uint32_t* Ps = smw + PS_OFF;

    int bh = blockIdx.y;
    int b = bh >> 3, h = bh & 7;
    int i0 = blockIdx.x * 128;
    const uint32_t* qb = qkvw + ((size_t)b * 1536 + h * 64) * 512;
    const uint32_t* kb = qb + (size_t)512 * 512;
    const uint32_t* vb = qb + (size_t)1024 * 512;

    int tid = threadIdx.x;
    int wid = tid >> 5, lane = tid & 31;
    int g = lane >> 2, tg = lane & 3;
    int r0 = wid * 16;
    uint32_t* Psw = Ps + r0 * PP;

    // load Q tile: word(d2, i) via prmt interleave of rows 2d2, 2d2+1
    #pragma unroll
    for (int it = 0; it < 2; it++) {
        int idx = it * 256 + tid;
        int d2 = idx >> 4, ch = idx & 15;
        uint4 a = *(const uint4*)(qb + (size_t)(2 * d2) * 512 + (i0 >> 1) + ch * 4);
        uint4 c = *(const uint4*)(qb + (size_t)(2 * d2 + 1) * 512 + (i0 >> 1) + ch * 4);
        *(uint4*)(Qs + d2 * PQ + ch * 8) = make_uint4(
            prmt(a.x, c.x, 0x5410), prmt(a.x, c.x, 0x7632),
            prmt(a.y, c.y, 0x5410), prmt(a.y, c.y, 0x7632));
        *(uint4*)(Qs + d2 * PQ + ch * 8 + 4) = make_uint4(
            prmt(a.z, c.z, 0x5410), prmt(a.z, c.z, 0x7632),
            prmt(a.w, c.w, 0x5410), prmt(a.w, c.w, 0x7632));
    }

    float m0 = -1e30f, m1 = -1e30f, l0 = 0.f, l1 = 0.f;
    float o_acc[8][4];
    #pragma unroll
    for (int nf = 0; nf < 8; nf++)
        #pragma unroll
        for (int i = 0; i < 4; i++) o_acc[nf][i] = 0.f;

    for (int j0 = 0; j0 < N_; j0 += 128) {
        __syncthreads();
        #pragma unroll
        for (int it = 0; it < 2; it++) {
            int idx = it * 256 + tid;
            int d2 = idx >> 4, ch = idx & 15;
            uint4 a = *(const uint4*)(kb + (size_t)(2 * d2) * 512 + (j0 >> 1) + ch * 4);
            uint4 c = *(const uint4*)(kb + (size_t)(2 * d2 + 1) * 512 + (j0 >> 1) + ch * 4);
            *(uint4*)(Ks + d2 * PQ + ch * 8) = make_uint4(
                prmt(a.x, c.x, 0x5410), prmt(a.x, c.x, 0x7632),
                prmt(a.y, c.y, 0x5410), prmt(a.y, c.y, 0x7632));
            *(uint4*)(Ks + d2 * PQ + ch * 8 + 4) = make_uint4(
                prmt(a.z, c.z, 0x5410), prmt(a.z, c.z, 0x7632),
                prmt(a.w, c.w, 0x5410), prmt(a.w, c.w, 0x7632));
        }
        #pragma unroll
        for (int it = 0; it < 4; it++) {
            int idx = it * 256 + tid;
            int d = idx >> 4, ch = idx & 15;
            uint4 v = *(const uint4*)(vb + (size_t)d * 512 + (j0 >> 1) + ch * 4);
            Vs[(ch * 4 + 0) * PV + d] = v.x;
            Vs[(ch * 4 + 1) * PV + d] = v.y;
            Vs[(ch * 4 + 2) * PV + d] = v.z;
            Vs[(ch * 4 + 3) * PV + d] = v.w;
        }
        __syncthreads();

        float acc[16][4];
        #pragma unroll
        for (int nf = 0; nf < 16; nf++)
            #pragma unroll
            for (int i = 0; i < 4; i++) acc[nf][i] = 0.f;

        #pragma unroll
        for (int kk = 0; kk < 32; kk += 8) {
            uint32_t a[4];
            a[0] = Qs[(kk + tg) * PQ + r0 + g];
            a[1] = Qs[(kk + tg) * PQ + r0 + g + 8];
            a[2] = Qs[(kk + tg + 4) * PQ + r0 + g];
            a[3] = Qs[(kk + tg + 4) * PQ + r0 + g + 8];
            #pragma unroll
            for (int nf = 0; nf < 16; nf++) {
                uint32_t bf[2];
                bf[0] = Ks[(kk + tg) * PQ + nf * 8 + g];
                bf[1] = Ks[(kk + tg + 4) * PQ + nf * 8 + g];
                mma_bf16(acc[nf], a, bf);
            }
        }

        float rm0 = -1e30f, rm1 = -1e30f;
        #pragma unroll
        for (int nf = 0; nf < 16; nf++) {
            rm0 = fmaxf(rm0, fmaxf(acc[nf][0], acc[nf][1]));
            rm1 = fmaxf(rm1, fmaxf(acc[nf][2], acc[nf][3]));
        }
        rm0 = fmaxf(rm0, __shfl_xor_sync(0xffffffffu, rm0, 1));
        rm0 = fmaxf(rm0, __shfl_xor_sync(0xffffffffu, rm0, 2));
        rm1 = fmaxf(rm1, __shfl_xor_sync(0xffffffffu, rm1, 1));
        rm1 = fmaxf(rm1, __shfl_xor_sync(0xffffffffu, rm1, 2));
        float mn0 = fmaxf(m0, rm0), mn1 = fmaxf(m1, rm1);
        float c0 = ex2((m0 - mn0) * K8), c1 = ex2((m1 - mn1) * K8);
        l0 *= c0; l1 *= c1;
        #pragma unroll
        for (int nf = 0; nf < 8; nf++) {
            o_acc[nf][0] *= c0; o_acc[nf][1] *= c0;
            o_acc[nf][2] *= c1; o_acc[nf][3] *= c1;
        }
        float s0 = 0.f, s1 = 0.f;
        #pragma unroll
        for (int nf = 0; nf < 16; nf++) {
            float p0 = ex2((acc[nf][0] - mn0) * K8);
            float p1 = ex2((acc[nf][1] - mn0) * K8);
            float p2 = ex2((acc[nf][2] - mn1) * K8);
            float p3 = ex2((acc[nf][3] - mn1) * K8);
            s0 += p0 + p1; s1 += p2 + p3;
            Psw[g * PP + nf * 4 + tg]       = bf2(p0, p1);
            Psw[(g + 8) * PP + nf * 4 + tg] = bf2(p2, p3);
        }
        s0 += __shfl_xor_sync(0xffffffffu, s0, 1);
        s0 += __shfl_xor_sync(0xffffffffu, s0, 2);
        s1 += __shfl_xor_sync(0xffffffffu, s1, 1);
        s1 += __shfl_xor_sync(0xffffffffu, s1, 2);
        l0 += s0; l1 += s1; m0 = mn0; m1 = mn1;
        __syncwarp();

        #pragma unroll
        for (int kk = 0; kk < 64; kk += 8) {
            uint32_t a[4];
            a[0] = Psw[g * PP + kk + tg];
            a[1] = Psw[(g + 8) * PP + kk + tg];
            a[2] = Psw[g * PP + kk + tg + 4];
            a[3] = Psw[(g + 8) * PP + kk + tg + 4];
            #pragma unroll
            for (int nf = 0; nf < 8; nf++) {
                uint32_t bf[2];
                bf[0] = Vs[(kk + tg) * PV + nf * 8 + g];
                bf[1] = Vs[(kk + tg + 4) * PV + nf * 8 + g];
                mma_bf16(o_acc[nf], a, bf);
            }
        }
        __syncwarp();
    }

    float inv0 = 1.f / l0, inv1 = 1.f / l1;
    #pragma unroll
    for (int nf = 0; nf < 8; nf++) {
        int d2 = nf * 4 + tg;
        Psw[g * 37 + d2]       = bf2(o_acc[nf][0] * inv0, o_acc[nf][1] * inv0);
        Psw[(g + 8) * 37 + d2] = bf2(o_acc[nf][2] * inv1, o_acc[nf][3] * inv1);
    }
    __syncwarp();
    uint32_t* aob = aow + ((size_t)(b * 256 + h * 32)) * 1024;
    #pragma unroll
    for (int it = 0; it < 16; it++) {
        int idx = it * 32 + lane;
        int iloc = idx & 15, d2 = idx >> 4;
        aob[(size_t)d2 * 1024 + i0 + r0 + iloc] = Psw[iloc * 37 + d2];
    }
}

// ---------------------------------------------------------------------------
extern "C" void kernel_launch(void* const* d_in, const int* in_sizes, int n_in,
                              void* d_out, int out_size) {
    const float* x      = (const float*)d_in[0];
    const float* gn_w   = (const float*)d_in[1];
    const float* gn_b   = (const float*)d_in[2];
    const float* qkv_w  = (const float*)d_in[3];
    const float* qkv_b  = (const float*)d_in[4];
    const float* proj_w = (const float*)d_in[5];
    const float* proj_b = (const float*)d_in[6];
    float* out = (float*)d_out;

    uint32_t *hbuf, *qkvbuf, *aobuf, *wq, *wp;
    cudaGetSymbolAddress((void**)&hbuf,   g_h);
    cudaGetSymbolAddress((void**)&qkvbuf, g_qkvw);
    cudaGetSymbolAddress((void**)&aobuf,  g_aow);
    cudaGetSymbolAddress((void**)&wq,     g_wq);
    cudaGetSymbolAddress((void**)&wp,     g_wp);

    cudaFuncSetAttribute(attn_tc, cudaFuncAttributeMaxDynamicSharedMemorySize, ATT_SMEM);
    cudaFuncSetAttribute(tc_gemm<false>, cudaFuncAttributeMaxDynamicSharedMemorySize, GM_SMEM);
    cudaFuncSetAttribute(tc_gemm<true>,  cudaFuncAttributeMaxDynamicSharedMemorySize, GM_SMEM);

    // 0) weight conversion (fp32 -> bf16 words)
    wconv<<<768, 256>>>((const float4*)qkv_w, (uint2*)wq, 1536 * 128);
    wconv<<<256, 256>>>((const float4*)proj_w, (uint2*)wp, 512 * 128);
    // 1) GroupNorm -> bf16 pair words
    gn_kernel<<<B_ * GROUPS, 256>>>(x, gn_w, gn_b);
    // 2) QKV GEMM (bf16 mma.sync, 3-stage cp.async + ldmatrix)
    tc_gemm<false><<<dim3(8, 12, B_), 256, GM_SMEM>>>(wq, qkv_b, hbuf, nullptr,
                                                      nullptr, qkvbuf, 1536);
    // 3) Flash attention (bf16 mma.sync, ex2.approx)
    attn_tc<<<dim3(8, B_ * HEADS), 256, ATT_SMEM>>>(qkvbuf, aobuf);
    // 4) Proj GEMM + bias + residual (bf16 mma.sync) -> fp32 out
    tc_gemm<true><<<dim3(8, 4, B_), 256, GM_SMEM>>>(wp, proj_b, aobuf, x,
                                                    out, nullptr, 512);
}

// round 12
// speedup vs baseline: 1.0823x; 1.0823x over previous
#include <cuda_runtime.h>
#include <cstdint>

// Problem constants
#define B_    8
#define C_    512
#define N_    1024
#define HEADS 8
#define DH    64
#define GROUPS 32

// Scratch (allocation-free: device globals). All bf16 pair-packed as u32 words.
// g_h / g_aow: k-major pair words: buf[(b*1024 + n)*256 + kp] = (v[2kp,n], v[2kp+1,n])
__device__ uint32_t g_h[(size_t)B_ * 1024 * 256];     // GN out            (8 MB)
__device__ uint32_t g_qkvw[(size_t)B_ * 1536 * 512];  // qkv [row][n/2]    (25 MB)
__device__ uint32_t g_aow[(size_t)B_ * 1024 * 256];   // attn out          (8 MB)
__device__ uint32_t g_wq[1536 * 256];                 // qkv_w bf16
__device__ uint32_t g_wp[512 * 256];                  // proj_w bf16

// ---------------------------------------------------------------------------
// helpers (plain sm_80+ PTX — safe for the sm_103 compile target)
// ---------------------------------------------------------------------------
__device__ __forceinline__ void mma_bf16(float* c, const uint32_t* a, const uint32_t* b) {
    asm("mma.sync.aligned.m16n8k16.row.col.f32.bf16.bf16.f32 "
        "{%0,%1,%2,%3}, {%4,%5,%6,%7}, {%8,%9}, {%0,%1,%2,%3};"
        : "+f"(c[0]), "+f"(c[1]), "+f"(c[2]), "+f"(c[3])
        : "r"(a[0]), "r"(a[1]), "r"(a[2]), "r"(a[3]), "r"(b[0]), "r"(b[1]));
}
__device__ __forceinline__ void ldsm4(uint32_t* r, uint32_t addr) {
    asm volatile("ldmatrix.sync.aligned.m8n8.x4.shared.b16 {%0,%1,%2,%3}, [%4];"
                 : "=r"(r[0]), "=r"(r[1]), "=r"(r[2]), "=r"(r[3]) : "r"(addr));
}
__device__ __forceinline__ uint32_t bf2(float lo, float hi) {   // word: lo16=lo
    uint32_t w;
    asm("cvt.rn.satfinite.bf16x2.f32 %0, %1, %2;" : "=r"(w) : "f"(hi), "f"(lo));
    return w;
}
__device__ __forceinline__ uint32_t prmt(uint32_t a, uint32_t b, uint32_t s) {
    uint32_t d;
    asm("prmt.b32 %0, %1, %2, %3;" : "=r"(d) : "r"(a), "r"(b), "r"(s));
    return d;
}
__device__ __forceinline__ float ex2(float x) {
    float r;
    asm("ex2.approx.f32 %0, %1;" : "=f"(r) : "f"(x));
    return r;
}
__device__ __forceinline__ uint32_t smem_u32(const void* p) {
    uint32_t a;
    asm("{ .reg .u64 t; cvta.to.shared.u64 t, %1; cvt.u32.u64 %0, t; }"
        : "=r"(a) : "l"(p));
    return a;
}
__device__ __forceinline__ void cp16(uint32_t dst, const void* src) {
    asm volatile("cp.async.cg.shared.global [%0], [%1], 16;" :: "r"(dst), "l"(src));
}
#define CP_COMMIT() asm volatile("cp.async.commit_group;" ::: "memory")
#define CP_WAIT(n)  asm volatile("cp.async.wait_group %0;" :: "n"(n) : "memory")

// ---------------------------------------------------------------------------
// Weight conversion: fp32 row-major -> bf16 pair words (same layout)
// ---------------------------------------------------------------------------
__global__ __launch_bounds__(256)
void wconv(const float4* __restrict__ src, uint2* __restrict__ dst, int n4) {
    int i = blockIdx.x * 256 + threadIdx.x;
    if (i < n4) {
        float4 v = src[i];
        dst[i] = make_uint2(bf2(v.x, v.y), bf2(v.z, v.w));
    }
}

// ---------------------------------------------------------------------------
// GroupNorm -> k-major pair words: g_h[(b*1024+n)*256 + kp]
// Block (b,g) owns kp = g*8..g*8+7 (16 channels), all 1024 n.
// ---------------------------------------------------------------------------
__global__ __launch_bounds__(256)
void gn_kernel(const float* __restrict__ x, const float* __restrict__ w,
               const float* __restrict__ bb) {
    int bg = blockIdx.x;
    int b = bg >> 5, g = bg & 31;
    const float4* xp = (const float4*)(x + ((size_t)b * C_ + g * 16) * N_);

    float s = 0.f, s2 = 0.f;
    for (int idx = threadIdx.x; idx < 4096; idx += 256) {
        float4 v = xp[idx];
        s  += v.x + v.y + v.z + v.w;
        s2 += v.x * v.x + v.y * v.y + v.z * v.z + v.w * v.w;
    }
    #pragma unroll
    for (int off = 16; off; off >>= 1) {
        s  += __shfl_xor_sync(0xffffffffu, s, off);
        s2 += __shfl_xor_sync(0xffffffffu, s2, off);
    }
    __shared__ float sh[16];
    __shared__ float smu, srstd;
    int warp = threadIdx.x >> 5, lane = threadIdx.x & 31;
    if (lane == 0) { sh[warp] = s; sh[warp + 8] = s2; }
    __syncthreads();
    if (threadIdx.x == 0) {
        float ts = 0.f, ts2 = 0.f;
        #pragma unroll
        for (int i = 0; i < 8; i++) { ts += sh[i]; ts2 += sh[i + 8]; }
        float mu  = ts * (1.f / 16384.f);
        float var = ts2 * (1.f / 16384.f) - mu * mu;
        smu = mu;
        srstd = rsqrtf(var + 1e-5f);
    }
    __syncthreads();
    float mu = smu, rstd = srstd;

    int tid = threadIdx.x;
    float hv[16][4];
    #pragma unroll
    for (int cc = 0; cc < 16; cc++) {
        int c = g * 16 + cc;
        float sc = w[c] * rstd, tc = bb[c] - mu * sc;
        float4 v = ((const float4*)(x + ((size_t)b * C_ + c) * N_))[tid];
        hv[cc][0] = v.x * sc + tc; hv[cc][1] = v.y * sc + tc;
        hv[cc][2] = v.z * sc + tc; hv[cc][3] = v.w * sc + tc;
    }
    uint32_t* hw = g_h + (size_t)b * 1024 * 256 + g * 8;
    #pragma unroll
    for (int k = 0; k < 4; k++) {
        uint4 w0, w1;
        w0.x = bf2(hv[0][k],  hv[1][k]);  w0.y = bf2(hv[2][k],  hv[3][k]);
        w0.z = bf2(hv[4][k],  hv[5][k]);  w0.w = bf2(hv[6][k],  hv[7][k]);
        w1.x = bf2(hv[8][k],  hv[9][k]);  w1.y = bf2(hv[10][k], hv[11][k]);
        w1.z = bf2(hv[12][k], hv[13][k]); w1.w = bf2(hv[14][k], hv[15][k]);
        *(uint4*)(hw + (size_t)(4 * tid + k) * 256)     = w0;
        *(uint4*)(hw + (size_t)(4 * tid + k) * 256 + 4) = w1;
    }
}

// ---------------------------------------------------------------------------
// bf16 mma.sync GEMM: 3-stage cp.async, ldmatrix for BOTH operands.
// CTA 128x128, 8 warps (2x4), warp tile 64x32, K-tile 32 (16 kp words).
// A: words [M][256]; B: k-major words [(b*1024+n)][256].
// ---------------------------------------------------------------------------
#define PA 20
#define STG_W (256 * PA)                      // 5120 words per stage
#define GM_SMEM (3 * STG_W * 4)               // 61,440 B

template <bool RES>
__global__ __launch_bounds__(256)
void tc_gemm(const uint32_t* __restrict__ A, const float* __restrict__ bias,
             const uint32_t* __restrict__ Bw, const float* __restrict__ X,
             float* __restrict__ OutF, uint32_t* __restrict__ OutW, int M) {
    extern __shared__ uint32_t smp[];

    int tid = threadIdx.x;
    int wid = tid >> 5, lane = tid & 31;
    int g = lane >> 2, tg = lane & 3;
    int warpM = wid >> 2, warpN = wid & 3;
    int wmRow = warpM * 64, wnCol = warpN * 32;

    // ldmatrix coords
    int rowin = lane & 7, matid = lane >> 3;
    int lmRow = wmRow + (matid & 1) * 8 + rowin;     // A: bit0->row, bit1->k8
    int lmKp  = (matid >> 1) * 4;
    int bRow  = wnCol + (matid >> 1) * 8 + rowin;    // B: bit1->row, bit0->k8
    int bKp   = (matid & 1) * 4;

    int b = blockIdx.z;
    int n0 = blockIdx.x * 128, o0 = blockIdx.y * 128;
    const uint32_t* Bp = Bw + (size_t)b * 1024 * 256;

    uint32_t sbase = smem_u32(smp);

    auto load_tile = [&](int t, int s) {
        uint32_t as = sbase + (uint32_t)(s * STG_W) * 4u;
        uint32_t bs = as + 128u * PA * 4u;
        #pragma unroll
        for (int it = 0; it < 2; it++) {
            int idx = it * 256 + tid;
            int o = idx >> 2, ch = idx & 3;
            cp16(as + (uint32_t)(o * PA + ch * 4) * 4u,
                 A + (size_t)(o0 + o) * 256 + t * 16 + ch * 4);
        }
        #pragma unroll
        for (int it = 0; it < 2; it++) {
            int idx = it * 256 + tid;
            int r = idx >> 2, ch = idx & 3;
            cp16(bs + (uint32_t)(r * PA + ch * 4) * 4u,
                 Bp + (size_t)(n0 + r) * 256 + t * 16 + ch * 4);
        }
        CP_COMMIT();
    };

    float acc[4][4][4];
    #pragma unroll
    for (int mf = 0; mf < 4; mf++)
        #pragma unroll
        for (int nf = 0; nf < 4; nf++)
            #pragma unroll
            for (int i = 0; i < 4; i++) acc[mf][nf][i] = 0.f;

    load_tile(0, 0);
    load_tile(1, 1);

    for (int t = 0; t < 16; t++) {
        if (t < 15) { CP_WAIT(1); } else { CP_WAIT(0); }
        __syncthreads();              // tile t visible; stage (t+2)%3 free
        if (t + 2 < 16) load_tile(t + 2, (t + 2) % 3);

        int s = t % 3;
        uint32_t aAddr = sbase + (uint32_t)(s * STG_W + lmRow * PA + lmKp) * 4u;
        uint32_t bAddr = sbase + (uint32_t)(s * STG_W + 128 * PA + bRow * PA + bKp) * 4u;

        #pragma unroll
        for (int ks = 0; ks < 2; ks++) {
            uint32_t a[4][4], bq[2][4];
            #pragma unroll
            for (int mf = 0; mf < 4; mf++)
                ldsm4(a[mf], aAddr + (uint32_t)(mf * 16 * PA + ks * 8) * 4u);
            #pragma unroll
            for (int np = 0; np < 2; np++)
                ldsm4(bq[np], bAddr + (uint32_t)(np * 16 * PA + ks * 8) * 4u);
            #pragma unroll
            for (int mf = 0; mf < 4; mf++)
                #pragma unroll
                for (int nf = 0; nf < 4; nf++)
                    mma_bf16(acc[mf][nf], a[mf], &bq[nf >> 1][(nf & 1) * 2]);
        }
    }

    #pragma unroll
    for (int mf = 0; mf < 4; mf++) {
        int r = o0 + wmRow + mf * 16 + g;
        float bi0 = bias[r], bi1 = bias[r + 8];
        if (RES) {
            size_t base0 = (size_t)b * M * N_ + (size_t)r * N_ + n0;
            size_t base1 = base0 + 8 * (size_t)N_;
            #pragma unroll
            for (int nf = 0; nf < 4; nf++) {
                int col = wnCol + nf * 8 + tg * 2;
                float2 v0 = make_float2(acc[mf][nf][0] + bi0, acc[mf][nf][1] + bi0);
                float2 v1 = make_float2(acc[mf][nf][2] + bi1, acc[mf][nf][3] + bi1);
                float2 x0 = *(const float2*)(X + base0 + col);
                float2 x1 = *(const float2*)(X + base1 + col);
                v0.x += x0.x; v0.y += x0.y;
                v1.x += x1.x; v1.y += x1.y;
                *(float2*)(OutF + base0 + col) = v0;
                *(float2*)(OutF + base1 + col) = v1;
            }
        } else {
            size_t w0 = ((size_t)b * 1536 + r) * 512;
            size_t w1 = w0 + 8 * 512;
            #pragma unroll
            for (int nf = 0; nf < 4; nf++) {
                int wc = ((n0 + wnCol + nf * 8) >> 1) + tg;
                OutW[w0 + wc] = bf2(acc[mf][nf][0] + bi0, acc[mf][nf][1] + bi0);
                OutW[w1 + wc] = bf2(acc[mf][nf][2] + bi1, acc[mf][nf][3] + bi1);
            }
        }
    }
}

// ---------------------------------------------------------------------------
// bf16 mma.sync flash attention. V smem XOR-swizzled (kills 16-way STS
// conflict); epilogue writes k-major g_aow via smem transpose (coalesced).
// ---------------------------------------------------------------------------
#define PQ 136
#define PV 72
#define PP 68
#define QS_OFF 0
#define KS_OFF (32 * PQ)
#define VS_OFF (2 * 32 * PQ)
#define PS_OFF (2 * 32 * PQ + 64 * PV)
#define ATT_SMEM ((PS_OFF + 128 * PP) * 4)    // 88,064 B
#define K8 0.18033688011112042f               // 0.125 * log2(e)

__global__ __launch_bounds__(256, 2)
void attn_tc(const uint32_t* __restrict__ qkvw, uint32_t* __restrict__ aow) {
    extern __shared__ uint32_t smw[];
    uint32_t* Qs = smw + QS_OFF;
    uint32_t* Ks = smw + KS_OFF;
    uint32_t* Vs = smw + VS_OFF;
    uint32_t* Ps = smw + PS_OFF;

    int bh = blockIdx.y;
    int b = bh >> 3, h = bh & 7;
    int i0 = blockIdx.x * 128;
    const uint32_t* qb = qkvw + ((size_t)b * 1536 + h * 64) * 512;
    const uint32_t* kb = qb + (size_t)512 * 512;
    const uint32_t* vb = qb + (size_t)1024 * 512;

    int tid = threadIdx.x;
    int wid = tid >> 5, lane = tid & 31;
    int g = lane >> 2, tg = lane & 3;
    int r0 = wid * 16;
    uint32_t* Psw = Ps + r0 * PP;

    // load Q tile: word(d2, i) via prmt interleave of rows 2d2, 2d2+1
    #pragma unroll
    for (int it = 0; it < 2; it++) {
        int idx = it * 256 + tid;
        int d2 = idx >> 4, ch = idx & 15;
        uint4 a = *(const uint4*)(qb + (size_t)(2 * d2) * 512 + (i0 >> 1) + ch * 4);
        uint4 c = *(const uint4*)(qb + (size_t)(2 * d2 + 1) * 512 + (i0 >> 1) + ch * 4);
        *(uint4*)(Qs + d2 * PQ + ch * 8) = make_uint4(
            prmt(a.x, c.x, 0x5410), prmt(a.x, c.x, 0x7632),
            prmt(a.y, c.y, 0x5410), prmt(a.y, c.y, 0x7632));
        *(uint4*)(Qs + d2 * PQ + ch * 8 + 4) = make_uint4(
            prmt(a.z, c.z, 0x5410), prmt(a.z, c.z, 0x7632),
            prmt(a.w, c.w, 0x5410), prmt(a.w, c.w, 0x7632));
    }

    float m0 = -1e30f, m1 = -1e30f, l0 = 0.f, l1 = 0.f;
    float o_acc[8][4];
    #pragma unroll
    for (int nf = 0; nf < 8; nf++)
        #pragma unroll
        for (int i = 0; i < 4; i++) o_acc[nf][i] = 0.f;

    for (int j0 = 0; j0 < N_; j0 += 128) {
        __syncthreads();
        #pragma unroll
        for (int it = 0; it < 2; it++) {
            int idx = it * 256 + tid;
            int d2 = idx >> 4, ch = idx & 15;
            uint4 a = *(const uint4*)(kb + (size_t)(2 * d2) * 512 + (j0 >> 1) + ch * 4);
            uint4 c = *(const uint4*)(kb + (size_t)(2 * d2 + 1) * 512 + (j0 >> 1) + ch * 4);
            *(uint4*)(Ks + d2 * PQ + ch * 8) = make_uint4(
                prmt(a.x, c.x, 0x5410), prmt(a.x, c.x, 0x7632),
                prmt(a.y, c.y, 0x5410), prmt(a.y, c.y, 0x7632));
            *(uint4*)(Ks + d2 * PQ + ch * 8 + 4) = make_uint4(
                prmt(a.z, c.z, 0x5410), prmt(a.z, c.z, 0x7632),
                prmt(a.w, c.w, 0x5410), prmt(a.w, c.w, 0x7632));
        }
        // V tile: word(j2, d) with XOR swizzle on d (conflict-free-ish STS)
        #pragma unroll
        for (int it = 0; it < 4; it++) {
            int idx = it * 256 + tid;
            int d = idx >> 4, ch = idx & 15;
            int swz = (ch & 7) | ((ch & 8) << 1);
            uint4 v = *(const uint4*)(vb + (size_t)d * 512 + (j0 >> 1) + ch * 4);
            Vs[(ch * 4 + 0) * PV + (d ^ swz)] = v.x;
            Vs[(ch * 4 + 1) * PV + (d ^ swz)] = v.y;
            Vs[(ch * 4 + 2) * PV + (d ^ swz)] = v.z;
            Vs[(ch * 4 + 3) * PV + (d ^ swz)] = v.w;
        }
        __syncthreads();

        float acc[16][4];
        #pragma unroll
        for (int nf = 0; nf < 16; nf++)
            #pragma unroll
            for (int i = 0; i < 4; i++) acc[nf][i] = 0.f;

        #pragma unroll
        for (int kk = 0; kk < 32; kk += 8) {
            uint32_t a[4];
            a[0] = Qs[(kk + tg) * PQ + r0 + g];
            a[1] = Qs[(kk + tg) * PQ + r0 + g + 8];
            a[2] = Qs[(kk + tg + 4) * PQ + r0 + g];
            a[3] = Qs[(kk + tg + 4) * PQ + r0 + g + 8];
            #pragma unroll
            for (int nf = 0; nf < 16; nf++) {
                uint32_t bf[2];
                bf[0] = Ks[(kk + tg) * PQ + nf * 8 + g];
                bf[1] = Ks[(kk + tg + 4) * PQ + nf * 8 + g];
                mma_bf16(acc[nf], a, bf);
            }
        }

        float rm0 = -1e30f, rm1 = -1e30f;
        #pragma unroll
        for (int nf = 0; nf < 16; nf++) {
            rm0 = fmaxf(rm0, fmaxf(acc[nf][0], acc[nf][1]));
            rm1 = fmaxf(rm1, fmaxf(acc[nf][2], acc[nf][3]));
        }
        rm0 = fmaxf(rm0, __shfl_xor_sync(0xffffffffu, rm0, 1));
        rm0 = fmaxf(rm0, __shfl_xor_sync(0xffffffffu, rm0, 2));
        rm1 = fmaxf(rm1, __shfl_xor_sync(0xffffffffu, rm1, 1));
        rm1 = fmaxf(rm1, __shfl_xor_sync(0xffffffffu, rm1, 2));
        float mn0 = fmaxf(m0, rm0), mn1 = fmaxf(m1, rm1);
        float c0 = ex2((m0 - mn0) * K8), c1 = ex2((m1 - mn1) * K8);
        l0 *= c0; l1 *= c1;
        #pragma unroll
        for (int nf = 0; nf < 8; nf++) {
            o_acc[nf][0] *= c0; o_acc[nf][1] *= c0;
            o_acc[nf][2] *= c1; o_acc[nf][3] *= c1;
        }
        float s0 = 0.f, s1 = 0.f;
        #pragma unroll
        for (int nf = 0; nf < 16; nf++) {
            float p0 = ex2((acc[nf][0] - mn0) * K8);
            float p1 = ex2((acc[nf][1] - mn0) * K8);
            float p2 = ex2((acc[nf][2] - mn1) * K8);
            float p3 = ex2((acc[nf][3] - mn1) * K8);
            s0 += p0 + p1; s1 += p2 + p3;
            Psw[g * PP + nf * 4 + tg]       = bf2(p0, p1);
            Psw[(g + 8) * PP + nf * 4 + tg] = bf2(p2, p3);
        }
        s0 += __shfl_xor_sync(0xffffffffu, s0, 1);
        s0 += __shfl_xor_sync(0xffffffffu, s0, 2);
        s1 += __shfl_xor_sync(0xffffffffu, s1, 1);
        s1 += __shfl_xor_sync(0xffffffffu, s1, 2);
        l0 += s0; l1 += s1; m0 = mn0; m1 = mn1;
        __syncwarp();

        #pragma unroll
        for (int kk = 0; kk < 64; kk += 8) {
            const int F0 = ((kk >> 2) & 7) | ((kk >> 5) << 4);
            const int F1 = (((kk + 4) >> 2) & 7) | (((kk + 4) >> 5) << 4);
            uint32_t a[4];
            a[0] = Psw[g * PP + kk + tg];
            a[1] = Psw[(g + 8) * PP + kk + tg];
            a[2] = Psw[g * PP + kk + tg + 4];
            a[3] = Psw[(g + 8) * PP + kk + tg + 4];
            #pragma unroll
            for (int nf = 0; nf < 8; nf++) {
                uint32_t bf[2];
                bf[0] = Vs[(kk + tg) * PV + ((nf * 8 + g) ^ F0)];
                bf[1] = Vs[(kk + 4 + tg) * PV + ((nf * 8 + g) ^ F1)];
                mma_bf16(o_acc[nf], a, bf);
            }
        }
        __syncwarp();
    }

    // epilogue: normalize -> Os[128 i][33] (reuse Ps) -> coalesced k-major store
    __syncthreads();
    float inv0 = 1.f / l0, inv1 = 1.f / l1;
    uint32_t* Os = Ps;
    #pragma unroll
    for (int nf = 0; nf < 8; nf++) {
        int d2 = nf * 4 + tg;
        Os[(r0 + g) * 33 + d2]     = bf2(o_acc[nf][0] * inv0, o_acc[nf][1] * inv0);
        Os[(r0 + g + 8) * 33 + d2] = bf2(o_acc[nf][2] * inv1, o_acc[nf][3] * inv1);
    }
    __syncthreads();
    uint32_t* aob = aow + (size_t)b * 1024 * 256 + h * 32;
    #pragma unroll
    for (int it = 0; it < 16; it++) {
        int idx = it * 256 + tid;
        int i = idx >> 5, c2 = idx & 31;
        aob[(size_t)(i0 + i) * 256 + c2] = Os[i * 33 + c2];
    }
}

// ---------------------------------------------------------------------------
extern "C" void kernel_launch(void* const* d_in, const int* in_sizes, int n_in,
                              void* d_out, int out_size) {
    const float* x      = (const float*)d_in[0];
    const float* gn_w   = (const float*)d_in[1];
    const float* gn_b   = (const float*)d_in[2];
    const float* qkv_w  = (const float*)d_in[3];
    const float* qkv_b  = (const float*)d_in[4];
    const float* proj_w = (const float*)d_in[5];
    const float* proj_b = (const float*)d_in[6];
    float* out = (float*)d_out;

    uint32_t *hbuf, *qkvbuf, *aobuf, *wq, *wp;
    cudaGetSymbolAddress((void**)&hbuf,   g_h);
    cudaGetSymbolAddress((void**)&qkvbuf, g_qkvw);
    cudaGetSymbolAddress((void**)&aobuf,  g_aow);
    cudaGetSymbolAddress((void**)&wq,     g_wq);
    cudaGetSymbolAddress((void**)&wp,     g_wp);

    cudaFuncSetAttribute(attn_tc, cudaFuncAttributeMaxDynamicSharedMemorySize, ATT_SMEM);
    cudaFuncSetAttribute(tc_gemm<false>, cudaFuncAttributeMaxDynamicSharedMemorySize, GM_SMEM);
    cudaFuncSetAttribute(tc_gemm<true>,  cudaFuncAttributeMaxDynamicSharedMemorySize, GM_SMEM);

    // 0) weight conversion (fp32 -> bf16 words)
    wconv<<<768, 256>>>((const float4*)qkv_w, (uint2*)wq, 1536 * 128);
    wconv<<<256, 256>>>((const float4*)proj_w, (uint2*)wp, 512 * 128);
    // 1) GroupNorm -> k-major bf16 pair words
    gn_kernel<<<B_ * GROUPS, 256>>>(x, gn_w, gn_b);
    // 2) QKV GEMM (bf16 mma.sync, dual-ldmatrix, 3-stage cp.async)
    tc_gemm<false><<<dim3(8, 12, B_), 256, GM_SMEM>>>(wq, qkv_b, hbuf, nullptr,
                                                      nullptr, qkvbuf, 1536);
    // 3) Flash attention (bf16 mma.sync, V-swizzle)
    attn_tc<<<dim3(8, B_ * HEADS), 256, ATT_SMEM>>>(qkvbuf, aobuf);
    // 4) Proj GEMM + bias + residual -> fp32 out
    tc_gemm<true><<<dim3(8, 4, B_), 256, GM_SMEM>>>(wp, proj_b, aobuf, x,
                                                    out, nullptr, 512);
}

// round 13
// speedup vs baseline: 1.1681x; 1.0793x over previous
#include <cuda_runtime.h>
#include <cstdint>

// Problem constants
#define B_    8
#define C_    512
#define N_    1024
#define HEADS 8
#define DH    64
#define GROUPS 32

// Scratch (allocation-free: device globals). All bf16 pair-packed as u32 words.
// g_h / g_aow: k-major pair words: buf[(b*1024 + n)*256 + kp] = (v[2kp,n], v[2kp+1,n])
__device__ uint32_t g_h[(size_t)B_ * 1024 * 256];     // GN out            (8 MB)
__device__ uint32_t g_qkvw[(size_t)B_ * 1536 * 512];  // qkv [row][n/2]    (25 MB)
__device__ uint32_t g_aow[(size_t)B_ * 1024 * 256];   // attn out          (8 MB)
__device__ uint32_t g_wq[1536 * 256];                 // qkv_w bf16
__device__ uint32_t g_wp[512 * 256];                  // proj_w bf16

// ---------------------------------------------------------------------------
// helpers (plain sm_80+ PTX — safe for the sm_103 compile target)
// ---------------------------------------------------------------------------
__device__ __forceinline__ void mma_bf16(float* c, const uint32_t* a, const uint32_t* b) {
    asm("mma.sync.aligned.m16n8k16.row.col.f32.bf16.bf16.f32 "
        "{%0,%1,%2,%3}, {%4,%5,%6,%7}, {%8,%9}, {%0,%1,%2,%3};"
        : "+f"(c[0]), "+f"(c[1]), "+f"(c[2]), "+f"(c[3])
        : "r"(a[0]), "r"(a[1]), "r"(a[2]), "r"(a[3]), "r"(b[0]), "r"(b[1]));
}
__device__ __forceinline__ void ldsm4(uint32_t* r, uint32_t addr) {
    asm volatile("ldmatrix.sync.aligned.m8n8.x4.shared.b16 {%0,%1,%2,%3}, [%4];"
                 : "=r"(r[0]), "=r"(r[1]), "=r"(r[2]), "=r"(r[3]) : "r"(addr));
}
__device__ __forceinline__ uint32_t bf2(float lo, float hi) {   // word: lo16=lo
    uint32_t w;
    asm("cvt.rn.satfinite.bf16x2.f32 %0, %1, %2;" : "=r"(w) : "f"(hi), "f"(lo));
    return w;
}
__device__ __forceinline__ uint32_t prmt(uint32_t a, uint32_t b, uint32_t s) {
    uint32_t d;
    asm("prmt.b32 %0, %1, %2, %3;" : "=r"(d) : "r"(a), "r"(b), "r"(s));
    return d;
}
__device__ __forceinline__ float ex2(float x) {
    float r;
    asm("ex2.approx.f32 %0, %1;" : "=f"(r) : "f"(x));
    return r;
}
__device__ __forceinline__ uint32_t smem_u32(const void* p) {
    uint32_t a;
    asm("{ .reg .u64 t; cvta.to.shared.u64 t, %1; cvt.u32.u64 %0, t; }"
        : "=r"(a) : "l"(p));
    return a;
}
__device__ __forceinline__ void cp16(uint32_t dst, const void* src) {
    asm volatile("cp.async.cg.shared.global [%0], [%1], 16;" :: "r"(dst), "l"(src));
}
#define CP_COMMIT() asm volatile("cp.async.commit_group;" ::: "memory")
#define CP_WAIT(n)  asm volatile("cp.async.wait_group %0;" :: "n"(n) : "memory")

// ---------------------------------------------------------------------------
// Weight conversion: fp32 row-major -> bf16 pair words (same layout)
// ---------------------------------------------------------------------------
__global__ __launch_bounds__(256)
void wconv(const float4* __restrict__ src, uint2* __restrict__ dst, int n4) {
    int i = blockIdx.x * 256 + threadIdx.x;
    if (i < n4) {
        float4 v = src[i];
        dst[i] = make_uint2(bf2(v.x, v.y), bf2(v.z, v.w));
    }
}

// ---------------------------------------------------------------------------
// GroupNorm -> k-major pair words: g_h[(b*1024+n)*256 + kp]
// ---------------------------------------------------------------------------
__global__ __launch_bounds__(256)
void gn_kernel(const float* __restrict__ x, const float* __restrict__ w,
               const float* __restrict__ bb) {
    int bg = blockIdx.x;
    int b = bg >> 5, g = bg & 31;
    const float4* xp = (const float4*)(x + ((size_t)b * C_ + g * 16) * N_);

    float s = 0.f, s2 = 0.f;
    for (int idx = threadIdx.x; idx < 4096; idx += 256) {
        float4 v = xp[idx];
        s  += v.x + v.y + v.z + v.w;
        s2 += v.x * v.x + v.y * v.y + v.z * v.z + v.w * v.w;
    }
    #pragma unroll
    for (int off = 16; off; off >>= 1) {
        s  += __shfl_xor_sync(0xffffffffu, s, off);
        s2 += __shfl_xor_sync(0xffffffffu, s2, off);
    }
    __shared__ float sh[16];
    __shared__ float smu, srstd;
    int warp = threadIdx.x >> 5, lane = threadIdx.x & 31;
    if (lane == 0) { sh[warp] = s; sh[warp + 8] = s2; }
    __syncthreads();
    if (threadIdx.x == 0) {
        float ts = 0.f, ts2 = 0.f;
        #pragma unroll
        for (int i = 0; i < 8; i++) { ts += sh[i]; ts2 += sh[i + 8]; }
        float mu  = ts * (1.f / 16384.f);
        float var = ts2 * (1.f / 16384.f) - mu * mu;
        smu = mu;
        srstd = rsqrtf(var + 1e-5f);
    }
    __syncthreads();
    float mu = smu, rstd = srstd;

    int tid = threadIdx.x;
    float hv[16][4];
    #pragma unroll
    for (int cc = 0; cc < 16; cc++) {
        int c = g * 16 + cc;
        float sc = w[c] * rstd, tc = bb[c] - mu * sc;
        float4 v = ((const float4*)(x + ((size_t)b * C_ + c) * N_))[tid];
        hv[cc][0] = v.x * sc + tc; hv[cc][1] = v.y * sc + tc;
        hv[cc][2] = v.z * sc + tc; hv[cc][3] = v.w * sc + tc;
    }
    uint32_t* hw = g_h + (size_t)b * 1024 * 256 + g * 8;
    #pragma unroll
    for (int k = 0; k < 4; k++) {
        uint4 w0, w1;
        w0.x = bf2(hv[0][k],  hv[1][k]);  w0.y = bf2(hv[2][k],  hv[3][k]);
        w0.z = bf2(hv[4][k],  hv[5][k]);  w0.w = bf2(hv[6][k],  hv[7][k]);
        w1.x = bf2(hv[8][k],  hv[9][k]);  w1.y = bf2(hv[10][k], hv[11][k]);
        w1.z = bf2(hv[12][k], hv[13][k]); w1.w = bf2(hv[14][k], hv[15][k]);
        *(uint4*)(hw + (size_t)(4 * tid + k) * 256)     = w0;
        *(uint4*)(hw + (size_t)(4 * tid + k) * 256 + 4) = w1;
    }
}

// ---------------------------------------------------------------------------
// bf16 mma.sync GEMM: 4-stage cp.async (wait_group 2 => ~3-iter lookahead),
// ldmatrix for BOTH operands. CTA 128x128, 8 warps, warp tile 64x32.
// ---------------------------------------------------------------------------
#define PA 20
#define STG_W (256 * PA)                      // 5120 words per stage
#define GM_SMEM (4 * STG_W * 4)               // 81,920 B

template <bool RES>
__global__ __launch_bounds__(256)
void tc_gemm(const uint32_t* __restrict__ A, const float* __restrict__ bias,
             const uint32_t* __restrict__ Bw, const float* __restrict__ X,
             float* __restrict__ OutF, uint32_t* __restrict__ OutW, int M) {
    extern __shared__ uint32_t smp[];

    int tid = threadIdx.x;
    int wid = tid >> 5, lane = tid & 31;
    int g = lane >> 2, tg = lane & 3;
    int warpM = wid >> 2, warpN = wid & 3;
    int wmRow = warpM * 64, wnCol = warpN * 32;

    int rowin = lane & 7, matid = lane >> 3;
    int lmRow = wmRow + (matid & 1) * 8 + rowin;
    int lmKp  = (matid >> 1) * 4;
    int bRow  = wnCol + (matid >> 1) * 8 + rowin;
    int bKp   = (matid & 1) * 4;

    int b = blockIdx.z;
    int n0 = blockIdx.x * 128, o0 = blockIdx.y * 128;
    const uint32_t* Bp = Bw + (size_t)b * 1024 * 256;

    uint32_t sbase = smem_u32(smp);

    auto load_tile = [&](int t, int s) {
        uint32_t as = sbase + (uint32_t)(s * STG_W) * 4u;
        uint32_t bs = as + 128u * PA * 4u;
        #pragma unroll
        for (int it = 0; it < 2; it++) {
            int idx = it * 256 + tid;
            int o = idx >> 2, ch = idx & 3;
            cp16(as + (uint32_t)(o * PA + ch * 4) * 4u,
                 A + (size_t)(o0 + o) * 256 + t * 16 + ch * 4);
        }
        #pragma unroll
        for (int it = 0; it < 2; it++) {
            int idx = it * 256 + tid;
            int r = idx >> 2, ch = idx & 3;
            cp16(bs + (uint32_t)(r * PA + ch * 4) * 4u,
                 Bp + (size_t)(n0 + r) * 256 + t * 16 + ch * 4);
        }
        CP_COMMIT();
    };

    float acc[4][4][4];
    #pragma unroll
    for (int mf = 0; mf < 4; mf++)
        #pragma unroll
        for (int nf = 0; nf < 4; nf++)
            #pragma unroll
            for (int i = 0; i < 4; i++) acc[mf][nf][i] = 0.f;

    load_tile(0, 0);
    load_tile(1, 1);
    load_tile(2, 2);

    for (int t = 0; t < 16; t++) {
        if (t <= 13)      { CP_WAIT(2); }
        else if (t == 14) { CP_WAIT(1); }
        else              { CP_WAIT(0); }
        __syncthreads();              // tile t visible; stage (t+3)%4 free
        if (t + 3 < 16) load_tile(t + 3, (t + 3) & 3);

        int s = t & 3;
        uint32_t aAddr = sbase + (uint32_t)(s * STG_W + lmRow * PA + lmKp) * 4u;
        uint32_t bAddr = sbase + (uint32_t)(s * STG_W + 128 * PA + bRow * PA + bKp) * 4u;

        #pragma unroll
        for (int ks = 0; ks < 2; ks++) {
            uint32_t a[4][4], bq[2][4];
            #pragma unroll
            for (int mf = 0; mf < 4; mf++)
                ldsm4(a[mf], aAddr + (uint32_t)(mf * 16 * PA + ks * 8) * 4u);
            #pragma unroll
            for (int np = 0; np < 2; np++)
                ldsm4(bq[np], bAddr + (uint32_t)(np * 16 * PA + ks * 8) * 4u);
            #pragma unroll
            for (int mf = 0; mf < 4; mf++)
                #pragma unroll
                for (int nf = 0; nf < 4; nf++)
                    mma_bf16(acc[mf][nf], a[mf], &bq[nf >> 1][(nf & 1) * 2]);
        }
    }

    #pragma unroll
    for (int mf = 0; mf < 4; mf++) {
        int r = o0 + wmRow + mf * 16 + g;
        float bi0 = bias[r], bi1 = bias[r + 8];
        if (RES) {
            size_t base0 = (size_t)b * M * N_ + (size_t)r * N_ + n0;
            size_t base1 = base0 + 8 * (size_t)N_;
            #pragma unroll
            for (int nf = 0; nf < 4; nf++) {
                int col = wnCol + nf * 8 + tg * 2;
                float2 v0 = make_float2(acc[mf][nf][0] + bi0, acc[mf][nf][1] + bi0);
                float2 v1 = make_float2(acc[mf][nf][2] + bi1, acc[mf][nf][3] + bi1);
                float2 x0 = *(const float2*)(X + base0 + col);
                float2 x1 = *(const float2*)(X + base1 + col);
                v0.x += x0.x; v0.y += x0.y;
                v1.x += x1.x; v1.y += x1.y;
                *(float2*)(OutF + base0 + col) = v0;
                *(float2*)(OutF + base1 + col) = v1;
            }
        } else {
            size_t w0 = ((size_t)b * 1536 + r) * 512;
            size_t w1 = w0 + 8 * 512;
            #pragma unroll
            for (int nf = 0; nf < 4; nf++) {
                int wc = ((n0 + wnCol + nf * 8) >> 1) + tg;
                OutW[w0 + wc] = bf2(acc[mf][nf][0] + bi0, acc[mf][nf][1] + bi0);
                OutW[w1 + wc] = bf2(acc[mf][nf][2] + bi1, acc[mf][nf][3] + bi1);
            }
        }
    }
}

// ---------------------------------------------------------------------------
// bf16 mma.sync flash attention.
// V tile: straight cp.async copy [d rows][j2 words, pitch 68] (global layout
// v[d][j2] is already (kp=j, n=d) k-major) + ldsm4 B-fragments; latency hidden
// behind S-mma + softmax (wait_group 0 + barrier before PV).
// ---------------------------------------------------------------------------
#define PQ 136
#define PV 68
#define PP 68
#define QS_OFF 0
#define KS_OFF (32 * PQ)
#define VS_OFF (2 * 32 * PQ)                  // 8704
#define PS_OFF (VS_OFF + 64 * PV)             // 13056
#define ATT_SMEM ((PS_OFF + 128 * PP) * 4)    // 87,040 B
#define K8 0.18033688011112042f               // 0.125 * log2(e)

__global__ __launch_bounds__(256, 2)
void attn_tc(const uint32_t* __restrict__ qkvw, uint32_t* __restrict__ aow) {
    extern __shared__ uint32_t smw[];
    uint32_t* Qs = smw + QS_OFF;
    uint32_t* Ks = smw + KS_OFF;
    uint32_t* Vs = smw + VS_OFF;
    uint32_t* Ps = smw + PS_OFF;

    int bh = blockIdx.y;
    int b = bh >> 3, h = bh & 7;
    int i0 = blockIdx.x * 128;
    const uint32_t* qb = qkvw + ((size_t)b * 1536 + h * 64) * 512;
    const uint32_t* kb = qb + (size_t)512 * 512;
    const uint32_t* vb = qb + (size_t)1024 * 512;

    int tid = threadIdx.x;
    int wid = tid >> 5, lane = tid & 31;
    int g = lane >> 2, tg = lane & 3;
    int rowin = lane & 7, matid = lane >> 3;
    int r0 = wid * 16;
    uint32_t* Psw = Ps + r0 * PP;
    uint32_t vsBase = smem_u32(Vs)
        + (uint32_t)((((matid >> 1) * 8 + rowin) * PV + (matid & 1) * 4) * 4);

    // load Q tile: word(d2, i) via prmt interleave of rows 2d2, 2d2+1
    #pragma unroll
    for (int it = 0; it < 2; it++) {
        int idx = it * 256 + tid;
        int d2 = idx >> 4, ch = idx & 15;
        uint4 a = *(const uint4*)(qb + (size_t)(2 * d2) * 512 + (i0 >> 1) + ch * 4);
        uint4 c = *(const uint4*)(qb + (size_t)(2 * d2 + 1) * 512 + (i0 >> 1) + ch * 4);
        *(uint4*)(Qs + d2 * PQ + ch * 8) = make_uint4(
            prmt(a.x, c.x, 0x5410), prmt(a.x, c.x, 0x7632),
            prmt(a.y, c.y, 0x5410), prmt(a.y, c.y, 0x7632));
        *(uint4*)(Qs + d2 * PQ + ch * 8 + 4) = make_uint4(
            prmt(a.z, c.z, 0x5410), prmt(a.z, c.z, 0x7632),
            prmt(a.w, c.w, 0x5410), prmt(a.w, c.w, 0x7632));
    }

    float m0 = -1e30f, m1 = -1e30f, l0 = 0.f, l1 = 0.f;
    float o_acc[8][4];
    #pragma unroll
    for (int nf = 0; nf < 8; nf++)
        #pragma unroll
        for (int i = 0; i < 4; i++) o_acc[nf][i] = 0.f;

    for (int j0 = 0; j0 < N_; j0 += 128) {
        __syncthreads();   // prev PV reads done; Ks/Vs free (Qs visible it.0)
        // V tile: straight async copy, consumed after softmax
        {
            int d = tid >> 2, ch = tid & 3;           // 4 chunks x 4 threads
            #pragma unroll
            for (int it = 0; it < 4; it++) {
                cp16(smem_u32(Vs) + (uint32_t)((d * PV + (ch * 4 + it * 16)) * 4),
                     vb + (size_t)d * 512 + (j0 >> 1) + ch * 4 + it * 16);
            }
            CP_COMMIT();
        }
        // K tile (prmt interleave, synchronous)
        #pragma unroll
        for (int it = 0; it < 2; it++) {
            int idx = it * 256 + tid;
            int d2 = idx >> 4, ch = idx & 15;
            uint4 a = *(const uint4*)(kb + (size_t)(2 * d2) * 512 + (j0 >> 1) + ch * 4);
            uint4 c = *(const uint4*)(kb + (size_t)(2 * d2 + 1) * 512 + (j0 >> 1) + ch * 4);
            *(uint4*)(Ks + d2 * PQ + ch * 8) = make_uint4(
                prmt(a.x, c.x, 0x5410), prmt(a.x, c.x, 0x7632),
                prmt(a.y, c.y, 0x5410), prmt(a.y, c.y, 0x7632));
            *(uint4*)(Ks + d2 * PQ + ch * 8 + 4) = make_uint4(
                prmt(a.z, c.z, 0x5410), prmt(a.z, c.z, 0x7632),
                prmt(a.w, c.w, 0x5410), prmt(a.w, c.w, 0x7632));
        }
        __syncthreads();

        // S = Q^T K
        float acc[16][4];
        #pragma unroll
        for (int nf = 0; nf < 16; nf++)
            #pragma unroll
            for (int i = 0; i < 4; i++) acc[nf][i] = 0.f;

        #pragma unroll
        for (int kk = 0; kk < 32; kk += 8) {
            uint32_t a[4];
            a[0] = Qs[(kk + tg) * PQ + r0 + g];
            a[1] = Qs[(kk + tg) * PQ + r0 + g + 8];
            a[2] = Qs[(kk + tg + 4) * PQ + r0 + g];
            a[3] = Qs[(kk + tg + 4) * PQ + r0 + g + 8];
            #pragma unroll
            for (int nf = 0; nf < 16; nf++) {
                uint32_t bf[2];
                bf[0] = Ks[(kk + tg) * PQ + nf * 8 + g];
                bf[1] = Ks[(kk + tg + 4) * PQ + nf * 8 + g];
                mma_bf16(acc[nf], a, bf);
            }
        }

        // online softmax
        float rm0 = -1e30f, rm1 = -1e30f;
        #pragma unroll
        for (int nf = 0; nf < 16; nf++) {
            rm0 = fmaxf(rm0, fmaxf(acc[nf][0], acc[nf][1]));
            rm1 = fmaxf(rm1, fmaxf(acc[nf][2], acc[nf][3]));
        }
        rm0 = fmaxf(rm0, __shfl_xor_sync(0xffffffffu, rm0, 1));
        rm0 = fmaxf(rm0, __shfl_xor_sync(0xffffffffu, rm0, 2));
        rm1 = fmaxf(rm1, __shfl_xor_sync(0xffffffffu, rm1, 1));
        rm1 = fmaxf(rm1, __shfl_xor_sync(0xffffffffu, rm1, 2));
        float mn0 = fmaxf(m0, rm0), mn1 = fmaxf(m1, rm1);
        float c0 = ex2((m0 - mn0) * K8), c1 = ex2((m1 - mn1) * K8);
        l0 *= c0; l1 *= c1;
        #pragma unroll
        for (int nf = 0; nf < 8; nf++) {
            o_acc[nf][0] *= c0; o_acc[nf][1] *= c0;
            o_acc[nf][2] *= c1; o_acc[nf][3] *= c1;
        }
        float s0 = 0.f, s1 = 0.f;
        #pragma unroll
        for (int nf = 0; nf < 16; nf++) {
            float p0 = ex2((acc[nf][0] - mn0) * K8);
            float p1 = ex2((acc[nf][1] - mn0) * K8);
            float p2 = ex2((acc[nf][2] - mn1) * K8);
            float p3 = ex2((acc[nf][3] - mn1) * K8);
            s0 += p0 + p1; s1 += p2 + p3;
            Psw[g * PP + nf * 4 + tg]       = bf2(p0, p1);
            Psw[(g + 8) * PP + nf * 4 + tg] = bf2(p2, p3);
        }
        s0 += __shfl_xor_sync(0xffffffffu, s0, 1);
        s0 += __shfl_xor_sync(0xffffffffu, s0, 2);
        s1 += __shfl_xor_sync(0xffffffffu, s1, 1);
        s1 += __shfl_xor_sync(0xffffffffu, s1, 2);
        l0 += s0; l1 += s1; m0 = mn0; m1 = mn1;

        CP_WAIT(0);
        __syncthreads();   // Vs visible to all warps; Psw visible in-warp

        // O += P @ V^T  (P: A operand from strip; V: ldsm4 B-fragments)
        #pragma unroll
        for (int kk = 0; kk < 8; kk++) {     // 8 steps of k=16 (jp step 8)
            int jp = kk * 8;
            uint32_t a[4];
            a[0] = Psw[g * PP + jp + tg];
            a[1] = Psw[(g + 8) * PP + jp + tg];
            a[2] = Psw[g * PP + jp + tg + 4];
            a[3] = Psw[(g + 8) * PP + jp + tg + 4];
            uint32_t bq[4][4];
            #pragma unroll
            for (int q = 0; q < 4; q++)
                ldsm4(bq[q], vsBase + (uint32_t)((q * 16 * PV + jp) * 4));
            #pragma unroll
            for (int nf = 0; nf < 8; nf++)
                mma_bf16(o_acc[nf], a, &bq[nf >> 1][(nf & 1) * 2]);
        }
    }

    // epilogue: normalize -> Os[128 i][33] (reuse Ps) -> coalesced k-major store
    __syncthreads();
    float inv0 = 1.f / l0, inv1 = 1.f / l1;
    uint32_t* Os = Ps;
    #pragma unroll
    for (int nf = 0; nf < 8; nf++) {
        int d2 = nf * 4 + tg;
        Os[(r0 + g) * 33 + d2]     = bf2(o_acc[nf][0] * inv0, o_acc[nf][1] * inv0);
        Os[(r0 + g + 8) * 33 + d2] = bf2(o_acc[nf][2] * inv1, o_acc[nf][3] * inv1);
    }
    __syncthreads();
    uint32_t* aob = aow + (size_t)b * 1024 * 256 + h * 32;
    #pragma unroll
    for (int it = 0; it < 16; it++) {
        int idx = it * 256 + tid;
        int i = idx >> 5, c2 = idx & 31;
        aob[(size_t)(i0 + i) * 256 + c2] = Os[i * 33 + c2];
    }
}

// ---------------------------------------------------------------------------
extern "C" void kernel_launch(void* const* d_in, const int* in_sizes, int n_in,
                              void* d_out, int out_size) {
    const float* x      = (const float*)d_in[0];
    const float* gn_w   = (const float*)d_in[1];
    const float* gn_b   = (const float*)d_in[2];
    const float* qkv_w  = (const float*)d_in[3];
    const float* qkv_b  = (const float*)d_in[4];
    const float* proj_w = (const float*)d_in[5];
    const float* proj_b = (const float*)d_in[6];
    float* out = (float*)d_out;

    uint32_t *hbuf, *qkvbuf, *aobuf, *wq, *wp;
    cudaGetSymbolAddress((void**)&hbuf,   g_h);
    cudaGetSymbolAddress((void**)&qkvbuf, g_qkvw);
    cudaGetSymbolAddress((void**)&aobuf,  g_aow);
    cudaGetSymbolAddress((void**)&wq,     g_wq);
    cudaGetSymbolAddress((void**)&wp,     g_wp);

    cudaFuncSetAttribute(attn_tc, cudaFuncAttributeMaxDynamicSharedMemorySize, ATT_SMEM);
    cudaFuncSetAttribute(tc_gemm<false>, cudaFuncAttributeMaxDynamicSharedMemorySize, GM_SMEM);
    cudaFuncSetAttribute(tc_gemm<true>,  cudaFuncAttributeMaxDynamicSharedMemorySize, GM_SMEM);

    // 0) weight conversion (fp32 -> bf16 words)
    wconv<<<768, 256>>>((const float4*)qkv_w, (uint2*)wq, 1536 * 128);
    wconv<<<256, 256>>>((const float4*)proj_w, (uint2*)wp, 512 * 128);
    // 1) GroupNorm -> k-major bf16 pair words
    gn_kernel<<<B_ * GROUPS, 256>>>(x, gn_w, gn_b);
    // 2) QKV GEMM (bf16 mma.sync, dual-ldmatrix, 4-stage cp.async)
    tc_gemm<false><<<dim3(8, 12, B_), 256, GM_SMEM>>>(wq, qkv_b, hbuf, nullptr,
                                                      nullptr, qkvbuf, 1536);
    // 3) Flash attention (bf16 mma.sync, async V + ldsm fragments)
    attn_tc<<<dim3(8, B_ * HEADS), 256, ATT_SMEM>>>(qkvbuf, aobuf);
    // 4) Proj GEMM + bias + residual -> fp32 out
    tc_gemm<true><<<dim3(8, 4, B_), 256, GM_SMEM>>>(wp, proj_b, aobuf, x,
                                                    out, nullptr, 512);
}

// round 14
// speedup vs baseline: 1.2478x; 1.0682x over previous
#include <cuda_runtime.h>
#include <cstdint>

// Problem constants
#define B_    8
#define C_    512
#define N_    1024
#define HEADS 8
#define DH    64
#define GROUPS 32

// Scratch (allocation-free: device globals). All bf16 pair-packed as u32 words.
// g_h / g_aow: k-major pair words: buf[(b*1024 + n)*256 + kp] = (v[2kp,n], v[2kp+1,n])
__device__ uint32_t g_h[(size_t)B_ * 1024 * 256];     // GN out            (8 MB)
__device__ uint32_t g_qkvw[(size_t)B_ * 1536 * 512];  // qkv [row][n/2]    (25 MB)
__device__ uint32_t g_aow[(size_t)B_ * 1024 * 256];   // attn out          (8 MB)
__device__ uint32_t g_wq[1536 * 256];                 // qkv_w bf16
__device__ uint32_t g_wp[512 * 256];                  // proj_w bf16

// ---------------------------------------------------------------------------
// helpers (plain sm_80+ PTX — safe for the sm_103 compile target)
// ---------------------------------------------------------------------------
__device__ __forceinline__ void mma_bf16(float* c, const uint32_t* a, const uint32_t* b) {
    asm("mma.sync.aligned.m16n8k16.row.col.f32.bf16.bf16.f32 "
        "{%0,%1,%2,%3}, {%4,%5,%6,%7}, {%8,%9}, {%0,%1,%2,%3};"
        : "+f"(c[0]), "+f"(c[1]), "+f"(c[2]), "+f"(c[3])
        : "r"(a[0]), "r"(a[1]), "r"(a[2]), "r"(a[3]), "r"(b[0]), "r"(b[1]));
}
__device__ __forceinline__ void ldsm4(uint32_t* r, uint32_t addr) {
    asm volatile("ldmatrix.sync.aligned.m8n8.x4.shared.b16 {%0,%1,%2,%3}, [%4];"
                 : "=r"(r[0]), "=r"(r[1]), "=r"(r[2]), "=r"(r[3]) : "r"(addr));
}
__device__ __forceinline__ uint32_t bf2(float lo, float hi) {   // word: lo16=lo
    uint32_t w;
    asm("cvt.rn.satfinite.bf16x2.f32 %0, %1, %2;" : "=r"(w) : "f"(hi), "f"(lo));
    return w;
}
__device__ __forceinline__ uint32_t prmt(uint32_t a, uint32_t b, uint32_t s) {
    uint32_t d;
    asm("prmt.b32 %0, %1, %2, %3;" : "=r"(d) : "r"(a), "r"(b), "r"(s));
    return d;
}
__device__ __forceinline__ float ex2(float x) {
    float r;
    asm("ex2.approx.f32 %0, %1;" : "=f"(r) : "f"(x));
    return r;
}
__device__ __forceinline__ uint32_t smem_u32(const void* p) {
    uint32_t a;
    asm("{ .reg .u64 t; cvta.to.shared.u64 t, %1; cvt.u32.u64 %0, t; }"
        : "=r"(a) : "l"(p));
    return a;
}
__device__ __forceinline__ void cp16(uint32_t dst, const void* src) {
    asm volatile("cp.async.cg.shared.global [%0], [%1], 16;" :: "r"(dst), "l"(src));
}
#define CP_COMMIT() asm volatile("cp.async.commit_group;" ::: "memory")
#define CP_WAIT(n)  asm volatile("cp.async.wait_group %0;" :: "n"(n) : "memory")

// ---------------------------------------------------------------------------
// Weight conversion (both weights in one launch)
// ---------------------------------------------------------------------------
#define WQ4 (1536 * 128)
#define WP4 (512 * 128)
__global__ __launch_bounds__(256)
void wconv2(const float4* __restrict__ qw, const float4* __restrict__ pw,
            uint2* __restrict__ dq, uint2* __restrict__ dp) {
    int i = blockIdx.x * 256 + threadIdx.x;
    if (i < WQ4) {
        float4 v = qw[i];
        dq[i] = make_uint2(bf2(v.x, v.y), bf2(v.z, v.w));
    } else if (i - WQ4 < WP4) {
        float4 v = pw[i - WQ4];
        dp[i - WQ4] = make_uint2(bf2(v.x, v.y), bf2(v.z, v.w));
    }
}

// ---------------------------------------------------------------------------
// GroupNorm -> k-major pair words: g_h[(b*1024+n)*256 + kp]
// ---------------------------------------------------------------------------
__global__ __launch_bounds__(256)
void gn_kernel(const float* __restrict__ x, const float* __restrict__ w,
               const float* __restrict__ bb) {
    int bg = blockIdx.x;
    int b = bg >> 5, g = bg & 31;
    const float4* xp = (const float4*)(x + ((size_t)b * C_ + g * 16) * N_);

    float s = 0.f, s2 = 0.f;
    for (int idx = threadIdx.x; idx < 4096; idx += 256) {
        float4 v = xp[idx];
        s  += v.x + v.y + v.z + v.w;
        s2 += v.x * v.x + v.y * v.y + v.z * v.z + v.w * v.w;
    }
    #pragma unroll
    for (int off = 16; off; off >>= 1) {
        s  += __shfl_xor_sync(0xffffffffu, s, off);
        s2 += __shfl_xor_sync(0xffffffffu, s2, off);
    }
    __shared__ float sh[16];
    __shared__ float smu, srstd;
    int warp = threadIdx.x >> 5, lane = threadIdx.x & 31;
    if (lane == 0) { sh[warp] = s; sh[warp + 8] = s2; }
    __syncthreads();
    if (threadIdx.x == 0) {
        float ts = 0.f, ts2 = 0.f;
        #pragma unroll
        for (int i = 0; i < 8; i++) { ts += sh[i]; ts2 += sh[i + 8]; }
        float mu  = ts * (1.f / 16384.f);
        float var = ts2 * (1.f / 16384.f) - mu * mu;
        smu = mu;
        srstd = rsqrtf(var + 1e-5f);
    }
    __syncthreads();
    float mu = smu, rstd = srstd;

    int tid = threadIdx.x;
    float hv[16][4];
    #pragma unroll
    for (int cc = 0; cc < 16; cc++) {
        int c = g * 16 + cc;
        float sc = w[c] * rstd, tc = bb[c] - mu * sc;
        float4 v = ((const float4*)(x + ((size_t)b * C_ + c) * N_))[tid];
        hv[cc][0] = v.x * sc + tc; hv[cc][1] = v.y * sc + tc;
        hv[cc][2] = v.z * sc + tc; hv[cc][3] = v.w * sc + tc;
    }
    uint32_t* hw = g_h + (size_t)b * 1024 * 256 + g * 8;
    #pragma unroll
    for (int k = 0; k < 4; k++) {
        uint4 w0, w1;
        w0.x = bf2(hv[0][k],  hv[1][k]);  w0.y = bf2(hv[2][k],  hv[3][k]);
        w0.z = bf2(hv[4][k],  hv[5][k]);  w0.w = bf2(hv[6][k],  hv[7][k]);
        w1.x = bf2(hv[8][k],  hv[9][k]);  w1.y = bf2(hv[10][k], hv[11][k]);
        w1.z = bf2(hv[12][k], hv[13][k]); w1.w = bf2(hv[14][k], hv[15][k]);
        *(uint4*)(hw + (size_t)(4 * tid + k) * 256)     = w0;
        *(uint4*)(hw + (size_t)(4 * tid + k) * 256 + 4) = w1;
    }
}

// ---------------------------------------------------------------------------
// bf16 mma.sync GEMM: K-tile 64 (half the barriers), 3-stage cp.async,
// ldmatrix both operands. CTA 128x128, 8 warps, warp tile 64x32.
// ---------------------------------------------------------------------------
#define PA 36
#define STG_W (256 * PA)                      // 9216 words per stage
#define GM_SMEM (3 * STG_W * 4)               // 110,592 B

template <bool RES>
__global__ __launch_bounds__(256)
void tc_gemm(const uint32_t* __restrict__ A, const float* __restrict__ bias,
             const uint32_t* __restrict__ Bw, const float* __restrict__ X,
             float* __restrict__ OutF, uint32_t* __restrict__ OutW, int M) {
    extern __shared__ uint32_t smp[];

    int tid = threadIdx.x;
    int wid = tid >> 5, lane = tid & 31;
    int g = lane >> 2, tg = lane & 3;
    int warpM = wid >> 2, warpN = wid & 3;
    int wmRow = warpM * 64, wnCol = warpN * 32;

    int rowin = lane & 7, matid = lane >> 3;
    int lmRow = wmRow + (matid & 1) * 8 + rowin;
    int lmKp  = (matid >> 1) * 4;
    int bRow  = wnCol + (matid >> 1) * 8 + rowin;
    int bKp   = (matid & 1) * 4;

    int b = blockIdx.z;
    int n0 = blockIdx.x * 128, o0 = blockIdx.y * 128;
    const uint32_t* Bp = Bw + (size_t)b * 1024 * 256;

    uint32_t sbase = smem_u32(smp);

    // K-tile 64: A/B each 128 rows x 32 kp words, pitch 36
    auto load_tile = [&](int t, int s) {
        uint32_t as = sbase + (uint32_t)(s * STG_W) * 4u;
        uint32_t bs = as + 128u * PA * 4u;
        #pragma unroll
        for (int it = 0; it < 4; it++) {
            int idx = it * 256 + tid;
            int o = idx >> 3, ch = idx & 7;
            cp16(as + (uint32_t)(o * PA + ch * 4) * 4u,
                 A + (size_t)(o0 + o) * 256 + t * 32 + ch * 4);
        }
        #pragma unroll
        for (int it = 0; it < 4; it++) {
            int idx = it * 256 + tid;
            int r = idx >> 3, ch = idx & 7;
            cp16(bs + (uint32_t)(r * PA + ch * 4) * 4u,
                 Bp + (size_t)(n0 + r) * 256 + t * 32 + ch * 4);
        }
        CP_COMMIT();
    };

    float acc[4][4][4];
    #pragma unroll
    for (int mf = 0; mf < 4; mf++)
        #pragma unroll
        for (int nf = 0; nf < 4; nf++)
            #pragma unroll
            for (int i = 0; i < 4; i++) acc[mf][nf][i] = 0.f;

    load_tile(0, 0);
    load_tile(1, 1);

    for (int t = 0; t < 8; t++) {
        if (t < 7) { CP_WAIT(1); } else { CP_WAIT(0); }
        __syncthreads();              // tile t visible; stage (t+2)%3 free
        if (t + 2 < 8) load_tile(t + 2, (t + 2) % 3);

        int s = t % 3;
        uint32_t aAddr = sbase + (uint32_t)(s * STG_W + lmRow * PA + lmKp) * 4u;
        uint32_t bAddr = sbase + (uint32_t)(s * STG_W + 128 * PA + bRow * PA + bKp) * 4u;

        #pragma unroll
        for (int ks = 0; ks < 4; ks++) {
            uint32_t a[4][4], bq[2][4];
            #pragma unroll
            for (int mf = 0; mf < 4; mf++)
                ldsm4(a[mf], aAddr + (uint32_t)(mf * 16 * PA + ks * 8) * 4u);
            #pragma unroll
            for (int np = 0; np < 2; np++)
                ldsm4(bq[np], bAddr + (uint32_t)(np * 16 * PA + ks * 8) * 4u);
            #pragma unroll
            for (int mf = 0; mf < 4; mf++)
                #pragma unroll
                for (int nf = 0; nf < 4; nf++)
                    mma_bf16(acc[mf][nf], a[mf], &bq[nf >> 1][(nf & 1) * 2]);
        }
    }

    #pragma unroll
    for (int mf = 0; mf < 4; mf++) {
        int r = o0 + wmRow + mf * 16 + g;
        float bi0 = bias[r], bi1 = bias[r + 8];
        if (RES) {
            size_t base0 = (size_t)b * M * N_ + (size_t)r * N_ + n0;
            size_t base1 = base0 + 8 * (size_t)N_;
            #pragma unroll
            for (int nf = 0; nf < 4; nf++) {
                int col = wnCol + nf * 8 + tg * 2;
                float2 v0 = make_float2(acc[mf][nf][0] + bi0, acc[mf][nf][1] + bi0);
                float2 v1 = make_float2(acc[mf][nf][2] + bi1, acc[mf][nf][3] + bi1);
                float2 x0 = *(const float2*)(X + base0 + col);
                float2 x1 = *(const float2*)(X + base1 + col);
                v0.x += x0.x; v0.y += x0.y;
                v1.x += x1.x; v1.y += x1.y;
                *(float2*)(OutF + base0 + col) = v0;
                *(float2*)(OutF + base1 + col) = v1;
            }
        } else {
            size_t w0 = ((size_t)b * 1536 + r) * 512;
            size_t w1 = w0 + 8 * 512;
            #pragma unroll
            for (int nf = 0; nf < 4; nf++) {
                int wc = ((n0 + wnCol + nf * 8) >> 1) + tg;
                OutW[w0 + wc] = bf2(acc[mf][nf][0] + bi0, acc[mf][nf][1] + bi0);
                OutW[w1 + wc] = bf2(acc[mf][nf][2] + bi1, acc[mf][nf][3] + bi1);
            }
        }
    }
}

// ---------------------------------------------------------------------------
// bf16 mma.sync flash attention. K now fully async: cp.async raw K(t+1) into
// Kraw staging (issued with V(t), hidden behind S-mma+softmax); interleave is
// a cheap smem->smem prmt pass. V: cp.async + ldsm4 PV fragments (proven).
// ---------------------------------------------------------------------------
#define PQ 136
#define PV 68
#define PP 68
#define QS_OFF 0
#define KS_OFF (32 * PQ)
#define VS_OFF (2 * 32 * PQ)                  // 8704
#define PS_OFF (VS_OFF + 64 * PV)             // 13056
#define KR_OFF (PS_OFF + 128 * PP)            // 21760
#define ATT_SMEM ((KR_OFF + 64 * PV) * 4)     // 104,448 B
#define K8 0.18033688011112042f               // 0.125 * log2(e)

__global__ __launch_bounds__(256, 2)
void attn_tc(const uint32_t* __restrict__ qkvw, uint32_t* __restrict__ aow) {
    extern __shared__ uint32_t smw[];
    uint32_t* Qs   = smw + QS_OFF;
    uint32_t* Ks   = smw + KS_OFF;
    uint32_t* Vs   = smw + VS_OFF;
    uint32_t* Ps   = smw + PS_OFF;
    uint32_t* Kraw = smw + KR_OFF;

    int bh = blockIdx.y;
    int b = bh >> 3, h = bh & 7;
    int i0 = blockIdx.x * 128;
    const uint32_t* qb = qkvw + ((size_t)b * 1536 + h * 64) * 512;
    const uint32_t* kb = qb + (size_t)512 * 512;
    const uint32_t* vb = qb + (size_t)1024 * 512;

    int tid = threadIdx.x;
    int wid = tid >> 5, lane = tid & 31;
    int g = lane >> 2, tg = lane & 3;
    int rowin = lane & 7, matid = lane >> 3;
    int r0 = wid * 16;
    uint32_t* Psw = Ps + r0 * PP;
    uint32_t vsBase = smem_u32(Vs)
        + (uint32_t)((((matid >> 1) * 8 + rowin) * PV + (matid & 1) * 4) * 4);

    // async-copy helper coords for 64-row x 64-word tiles (V / Kraw)
    int cpD = tid >> 2, cpC = tid & 3;

    // issue raw K tile 0 ASAP
    {
        #pragma unroll
        for (int it = 0; it < 4; it++)
            cp16(smem_u32(Kraw) + (uint32_t)((cpD * PV + (cpC * 4 + it * 16)) * 4),
                 kb + (size_t)cpD * 512 + cpC * 4 + it * 16);
        CP_COMMIT();
    }

    // load Q tile: word(d2, i) via prmt interleave of rows 2d2, 2d2+1
    #pragma unroll
    for (int it = 0; it < 2; it++) {
        int idx = it * 256 + tid;
        int d2 = idx >> 4, ch = idx & 15;
        uint4 a = *(const uint4*)(qb + (size_t)(2 * d2) * 512 + (i0 >> 1) + ch * 4);
        uint4 c = *(const uint4*)(qb + (size_t)(2 * d2 + 1) * 512 + (i0 >> 1) + ch * 4);
        *(uint4*)(Qs + d2 * PQ + ch * 8) = make_uint4(
            prmt(a.x, c.x, 0x5410), prmt(a.x, c.x, 0x7632),
            prmt(a.y, c.y, 0x5410), prmt(a.y, c.y, 0x7632));
        *(uint4*)(Qs + d2 * PQ + ch * 8 + 4) = make_uint4(
            prmt(a.z, c.z, 0x5410), prmt(a.z, c.z, 0x7632),
            prmt(a.w, c.w, 0x5410), prmt(a.w, c.w, 0x7632));
    }

    float m0 = -1e30f, m1 = -1e30f, l0 = 0.f, l1 = 0.f;
    float o_acc[8][4];
    #pragma unroll
    for (int nf = 0; nf < 8; nf++)
        #pragma unroll
        for (int i = 0; i < 4; i++) o_acc[nf][i] = 0.f;

    for (int j0 = 0; j0 < N_; j0 += 128) {
        CP_WAIT(0);        // Kraw(t) arrived (no-op for t>0: drained pre-PV)
        __syncthreads();   // Ks/Vs free (prev tiles consumed), Qs visible
        // interleave Kraw -> Ks (smem->smem prmt pass)
        #pragma unroll
        for (int it = 0; it < 2; it++) {
            int idx = it * 256 + tid;
            int d2 = idx >> 4, ch = idx & 15;
            uint4 a = *(const uint4*)(Kraw + (2 * d2) * PV + ch * 4);
            uint4 c = *(const uint4*)(Kraw + (2 * d2 + 1) * PV + ch * 4);
            *(uint4*)(Ks + d2 * PQ + ch * 8) = make_uint4(
                prmt(a.x, c.x, 0x5410), prmt(a.x, c.x, 0x7632),
                prmt(a.y, c.y, 0x5410), prmt(a.y, c.y, 0x7632));
            *(uint4*)(Ks + d2 * PQ + ch * 8 + 4) = make_uint4(
                prmt(a.z, c.z, 0x5410), prmt(a.z, c.z, 0x7632),
                prmt(a.w, c.w, 0x5410), prmt(a.w, c.w, 0x7632));
        }
        __syncthreads();   // Ks visible; Kraw consumed

        // issue V(t) + raw K(t+1); they land during S-mma + softmax
        #pragma unroll
        for (int it = 0; it < 4; it++)
            cp16(smem_u32(Vs) + (uint32_t)((cpD * PV + (cpC * 4 + it * 16)) * 4),
                 vb + (size_t)cpD * 512 + (j0 >> 1) + cpC * 4 + it * 16);
        if (j0 + 128 < N_) {
            #pragma unroll
            for (int it = 0; it < 4; it++)
                cp16(smem_u32(Kraw) + (uint32_t)((cpD * PV + (cpC * 4 + it * 16)) * 4),
                     kb + (size_t)cpD * 512 + ((j0 + 128) >> 1) + cpC * 4 + it * 16);
        }
        CP_COMMIT();

        // S = Q^T K
        float acc[16][4];
        #pragma unroll
        for (int nf = 0; nf < 16; nf++)
            #pragma unroll
            for (int i = 0; i < 4; i++) acc[nf][i] = 0.f;

        #pragma unroll
        for (int kk = 0; kk < 32; kk += 8) {
            uint32_t a[4];
            a[0] = Qs[(kk + tg) * PQ + r0 + g];
            a[1] = Qs[(kk + tg) * PQ + r0 + g + 8];
            a[2] = Qs[(kk + tg + 4) * PQ + r0 + g];
            a[3] = Qs[(kk + tg + 4) * PQ + r0 + g + 8];
            #pragma unroll
            for (int nf = 0; nf < 16; nf++) {
                uint32_t bf[2];
                bf[0] = Ks[(kk + tg) * PQ + nf * 8 + g];
                bf[1] = Ks[(kk + tg + 4) * PQ + nf * 8 + g];
                mma_bf16(acc[nf], a, bf);
            }
        }

        // online softmax
        float rm0 = -1e30f, rm1 = -1e30f;
        #pragma unroll
        for (int nf = 0; nf < 16; nf++) {
            rm0 = fmaxf(rm0, fmaxf(acc[nf][0], acc[nf][1]));
            rm1 = fmaxf(rm1, fmaxf(acc[nf][2], acc[nf][3]));
        }
        rm0 = fmaxf(rm0, __shfl_xor_sync(0xffffffffu, rm0, 1));
        rm0 = fmaxf(rm0, __shfl_xor_sync(0xffffffffu, rm0, 2));
        rm1 = fmaxf(rm1, __shfl_xor_sync(0xffffffffu, rm1, 1));
        rm1 = fmaxf(rm1, __shfl_xor_sync(0xffffffffu, rm1, 2));
        float mn0 = fmaxf(m0, rm0), mn1 = fmaxf(m1, rm1);
        float c0 = ex2((m0 - mn0) * K8), c1 = ex2((m1 - mn1) * K8);
        l0 *= c0; l1 *= c1;
        #pragma unroll
        for (int nf = 0; nf < 8; nf++) {
            o_acc[nf][0] *= c0; o_acc[nf][1] *= c0;
            o_acc[nf][2] *= c1; o_acc[nf][3] *= c1;
        }
        float s0 = 0.f, s1 = 0.f;
        #pragma unroll
        for (int nf = 0; nf < 16; nf++) {
            float p0 = ex2((acc[nf][0] - mn0) * K8);
            float p1 = ex2((acc[nf][1] - mn0) * K8);
            float p2 = ex2((acc[nf][2] - mn1) * K8);
            float p3 = ex2((acc[nf][3] - mn1) * K8);
            s0 += p0 + p1; s1 += p2 + p3;
            Psw[g * PP + nf * 4 + tg]       = bf2(p0, p1);
            Psw[(g + 8) * PP + nf * 4 + tg] = bf2(p2, p3);
        }
        s0 += __shfl_xor_sync(0xffffffffu, s0, 1);
        s0 += __shfl_xor_sync(0xffffffffu, s0, 2);
        s1 += __shfl_xor_sync(0xffffffffu, s1, 1);
        s1 += __shfl_xor_sync(0xffffffffu, s1, 2);
        l0 += s0; l1 += s1; m0 = mn0; m1 = mn1;

        CP_WAIT(0);
        __syncthreads();   // Vs (and Kraw t+1) visible; Psw visible in-warp

        // O += P @ V^T
        #pragma unroll
        for (int kk = 0; kk < 8; kk++) {
            int jp = kk * 8;
            uint32_t a[4];
            a[0] = Psw[g * PP + jp + tg];
            a[1] = Psw[(g + 8) * PP + jp + tg];
            a[2] = Psw[g * PP + jp + tg + 4];
            a[3] = Psw[(g + 8) * PP + jp + tg + 4];
            uint32_t bq[4][4];
            #pragma unroll
            for (int q = 0; q < 4; q++)
                ldsm4(bq[q], vsBase + (uint32_t)((q * 16 * PV + jp) * 4));
            #pragma unroll
            for (int nf = 0; nf < 8; nf++)
                mma_bf16(o_acc[nf], a, &bq[nf >> 1][(nf & 1) * 2]);
        }
    }

    // epilogue: normalize -> Os[128 i][33] (reuse Ps) -> coalesced k-major store
    __syncthreads();
    float inv0 = 1.f / l0, inv1 = 1.f / l1;
    uint32_t* Os = Ps;
    #pragma unroll
    for (int nf = 0; nf < 8; nf++) {
        int d2 = nf * 4 + tg;
        Os[(r0 + g) * 33 + d2]     = bf2(o_acc[nf][0] * inv0, o_acc[nf][1] * inv0);
        Os[(r0 + g + 8) * 33 + d2] = bf2(o_acc[nf][2] * inv1, o_acc[nf][3] * inv1);
    }
    __syncthreads();
    uint32_t* aob = aow + (size_t)b * 1024 * 256 + h * 32;
    #pragma unroll
    for (int it = 0; it < 16; it++) {
        int idx = it * 256 + tid;
        int i = idx >> 5, c2 = idx & 31;
        aob[(size_t)(i0 + i) * 256 + c2] = Os[i * 33 + c2];
    }
}

// ---------------------------------------------------------------------------
extern "C" void kernel_launch(void* const* d_in, const int* in_sizes, int n_in,
                              void* d_out, int out_size) {
    const float* x      = (const float*)d_in[0];
    const float* gn_w   = (const float*)d_in[1];
    const float* gn_b   = (const float*)d_in[2];
    const float* qkv_w  = (const float*)d_in[3];
    const float* qkv_b  = (const float*)d_in[4];
    const float* proj_w = (const float*)d_in[5];
    const float* proj_b = (const float*)d_in[6];
    float* out = (float*)d_out;

    uint32_t *hbuf, *qkvbuf, *aobuf, *wq, *wp;
    cudaGetSymbolAddress((void**)&hbuf,   g_h);
    cudaGetSymbolAddress((void**)&qkvbuf, g_qkvw);
    cudaGetSymbolAddress((void**)&aobuf,  g_aow);
    cudaGetSymbolAddress((void**)&wq,     g_wq);
    cudaGetSymbolAddress((void**)&wp,     g_wp);

    cudaFuncSetAttribute(attn_tc, cudaFuncAttributeMaxDynamicSharedMemorySize, ATT_SMEM);
    cudaFuncSetAttribute(tc_gemm<false>, cudaFuncAttributeMaxDynamicSharedMemorySize, GM_SMEM);
    cudaFuncSetAttribute(tc_gemm<true>,  cudaFuncAttributeMaxDynamicSharedMemorySize, GM_SMEM);

    // 0) weight conversion (both, one launch)
    wconv2<<<(WQ4 + WP4 + 255) / 256, 256>>>((const float4*)qkv_w, (const float4*)proj_w,
                                             (uint2*)wq, (uint2*)wp);
    // 1) GroupNorm -> k-major bf16 pair words
    gn_kernel<<<B_ * GROUPS, 256>>>(x, gn_w, gn_b);
    // 2) QKV GEMM (bf16 mma.sync, K-tile 64, 3-stage cp.async)
    tc_gemm<false><<<dim3(8, 12, B_), 256, GM_SMEM>>>(wq, qkv_b, hbuf, nullptr,
                                                      nullptr, qkvbuf, 1536);
    // 3) Flash attention (bf16 mma.sync, fully async K+V)
    attn_tc<<<dim3(8, B_ * HEADS), 256, ATT_SMEM>>>(qkvbuf, aobuf);
    // 4) Proj GEMM + bias + residual -> fp32 out
    tc_gemm<true><<<dim3(8, 4, B_), 256, GM_SMEM>>>(wp, proj_b, aobuf, x,
                                                    out, nullptr, 512);
}

// round 15
// speedup vs baseline: 1.3330x; 1.0683x over previous
#include <cuda_runtime.h>
#include <cstdint>

// Problem constants
#define B_    8
#define C_    512
#define N_    1024
#define HEADS 8
#define DH    64
#define GROUPS 32

// Scratch (allocation-free: device globals). All bf16 pair-packed as u32 words.
__device__ uint32_t g_h[(size_t)B_ * 1024 * 256];     // GN out, [n][kp]   (8 MB)
__device__ uint32_t g_qkvw[(size_t)B_ * 1536 * 512];  // v region used     (25 MB)
__device__ uint32_t g_qT[(size_t)B_ * 8 * 1024 * 32]; // q [b,h,i][d2]     (8 MB)
__device__ uint32_t g_kT[(size_t)B_ * 8 * 1024 * 32]; // k [b,h,i][d2]     (8 MB)
__device__ uint32_t g_aow[(size_t)B_ * 1024 * 256];   // attn out [n][kp]  (8 MB)
__device__ uint32_t g_wq[1536 * 256];                 // qkv_w bf16
__device__ uint32_t g_wp[512 * 256];                  // proj_w bf16

// ---------------------------------------------------------------------------
// helpers (plain sm_80+ PTX — safe for the sm_103 compile target)
// ---------------------------------------------------------------------------
__device__ __forceinline__ void mma_bf16(float* c, const uint32_t* a, const uint32_t* b) {
    asm("mma.sync.aligned.m16n8k16.row.col.f32.bf16.bf16.f32 "
        "{%0,%1,%2,%3}, {%4,%5,%6,%7}, {%8,%9}, {%0,%1,%2,%3};"
        : "+f"(c[0]), "+f"(c[1]), "+f"(c[2]), "+f"(c[3])
        : "r"(a[0]), "r"(a[1]), "r"(a[2]), "r"(a[3]), "r"(b[0]), "r"(b[1]));
}
__device__ __forceinline__ void ldsm4(uint32_t* r, uint32_t addr) {
    asm volatile("ldmatrix.sync.aligned.m8n8.x4.shared.b16 {%0,%1,%2,%3}, [%4];"
                 : "=r"(r[0]), "=r"(r[1]), "=r"(r[2]), "=r"(r[3]) : "r"(addr));
}
__device__ __forceinline__ uint32_t bf2(float lo, float hi) {   // word: lo16=lo
    uint32_t w;
    asm("cvt.rn.satfinite.bf16x2.f32 %0, %1, %2;" : "=r"(w) : "f"(hi), "f"(lo));
    return w;
}
__device__ __forceinline__ uint16_t bfh(float x) {
    uint16_t h;
    asm("cvt.rn.bf16.f32 %0, %1;" : "=h"(h) : "f"(x));
    return h;
}
__device__ __forceinline__ float ex2(float x) {
    float r;
    asm("ex2.approx.f32 %0, %1;" : "=f"(r) : "f"(x));
    return r;
}
__device__ __forceinline__ uint32_t smem_u32(const void* p) {
    uint32_t a;
    asm("{ .reg .u64 t; cvta.to.shared.u64 t, %1; cvt.u32.u64 %0, t; }"
        : "=r"(a) : "l"(p));
    return a;
}
__device__ __forceinline__ void cp16(uint32_t dst, const void* src) {
    asm volatile("cp.async.cg.shared.global [%0], [%1], 16;" :: "r"(dst), "l"(src));
}
#define CP_COMMIT() asm volatile("cp.async.commit_group;" ::: "memory")
#define CP_WAIT(n)  asm volatile("cp.async.wait_group %0;" :: "n"(n) : "memory")

// ---------------------------------------------------------------------------
// Weight conversion (both weights in one launch)
// ---------------------------------------------------------------------------
#define WQ4 (1536 * 128)
#define WP4 (512 * 128)
__global__ __launch_bounds__(256)
void wconv2(const float4* __restrict__ qw, const float4* __restrict__ pw,
            uint2* __restrict__ dq, uint2* __restrict__ dp) {
    int i = blockIdx.x * 256 + threadIdx.x;
    if (i < WQ4) {
        float4 v = qw[i];
        dq[i] = make_uint2(bf2(v.x, v.y), bf2(v.z, v.w));
    } else if (i - WQ4 < WP4) {
        float4 v = pw[i - WQ4];
        dp[i - WQ4] = make_uint2(bf2(v.x, v.y), bf2(v.z, v.w));
    }
}

// ---------------------------------------------------------------------------
// GroupNorm -> k-major pair words: g_h[(b*1024+n)*256 + kp]
// ---------------------------------------------------------------------------
__global__ __launch_bounds__(256)
void gn_kernel(const float* __restrict__ x, const float* __restrict__ w,
               const float* __restrict__ bb) {
    int bg = blockIdx.x;
    int b = bg >> 5, g = bg & 31;
    const float4* xp = (const float4*)(x + ((size_t)b * C_ + g * 16) * N_);

    float s = 0.f, s2 = 0.f;
    for (int idx = threadIdx.x; idx < 4096; idx += 256) {
        float4 v = xp[idx];
        s  += v.x + v.y + v.z + v.w;
        s2 += v.x * v.x + v.y * v.y + v.z * v.z + v.w * v.w;
    }
    #pragma unroll
    for (int off = 16; off; off >>= 1) {
        s  += __shfl_xor_sync(0xffffffffu, s, off);
        s2 += __shfl_xor_sync(0xffffffffu, s2, off);
    }
    __shared__ float sh[16];
    __shared__ float smu, srstd;
    int warp = threadIdx.x >> 5, lane = threadIdx.x & 31;
    if (lane == 0) { sh[warp] = s; sh[warp + 8] = s2; }
    __syncthreads();
    if (threadIdx.x == 0) {
        float ts = 0.f, ts2 = 0.f;
        #pragma unroll
        for (int i = 0; i < 8; i++) { ts += sh[i]; ts2 += sh[i + 8]; }
        float mu  = ts * (1.f / 16384.f);
        float var = ts2 * (1.f / 16384.f) - mu * mu;
        smu = mu;
        srstd = rsqrtf(var + 1e-5f);
    }
    __syncthreads();
    float mu = smu, rstd = srstd;

    int tid = threadIdx.x;
    float hv[16][4];
    #pragma unroll
    for (int cc = 0; cc < 16; cc++) {
        int c = g * 16 + cc;
        float sc = w[c] * rstd, tc = bb[c] - mu * sc;
        float4 v = ((const float4*)(x + ((size_t)b * C_ + c) * N_))[tid];
        hv[cc][0] = v.x * sc + tc; hv[cc][1] = v.y * sc + tc;
        hv[cc][2] = v.z * sc + tc; hv[cc][3] = v.w * sc + tc;
    }
    uint32_t* hw = g_h + (size_t)b * 1024 * 256 + g * 8;
    #pragma unroll
    for (int k = 0; k < 4; k++) {
        uint4 w0, w1;
        w0.x = bf2(hv[0][k],  hv[1][k]);  w0.y = bf2(hv[2][k],  hv[3][k]);
        w0.z = bf2(hv[4][k],  hv[5][k]);  w0.w = bf2(hv[6][k],  hv[7][k]);
        w1.x = bf2(hv[8][k],  hv[9][k]);  w1.y = bf2(hv[10][k], hv[11][k]);
        w1.z = bf2(hv[12][k], hv[13][k]); w1.w = bf2(hv[14][k], hv[15][k]);
        *(uint4*)(hw + (size_t)(4 * tid + k) * 256)     = w0;
        *(uint4*)(hw + (size_t)(4 * tid + k) * 256 + 4) = w1;
    }
}

// ---------------------------------------------------------------------------
// bf16 mma.sync GEMM: K-tile 64, 3-stage cp.async, ldmatrix both operands.
// RES=true : fp32 out + residual (proj).
// RES=false: qkv. v rows (blockIdx.y>=8) -> OutW [row][n/2]; q/k rows ->
//            transposed pair layout qT/kT[(b,h,i)][d2] via smem staging.
// ---------------------------------------------------------------------------
#define PA 36
#define STG_W (256 * PA)                      // 9216 words per stage
#define GM_SMEM (3 * STG_W * 4)               // 110,592 B

template <bool RES>
__global__ __launch_bounds__(256)
void tc_gemm(const uint32_t* __restrict__ A, const float* __restrict__ bias,
             const uint32_t* __restrict__ Bw, const float* __restrict__ X,
             float* __restrict__ OutF, uint32_t* __restrict__ OutW,
             uint32_t* __restrict__ qTo, uint32_t* __restrict__ kTo, int M) {
    extern __shared__ uint32_t smp[];

    int tid = threadIdx.x;
    int wid = tid >> 5, lane = tid & 31;
    int g = lane >> 2, tg = lane & 3;
    int warpM = wid >> 2, warpN = wid & 3;
    int wmRow = warpM * 64, wnCol = warpN * 32;

    int rowin = lane & 7, matid = lane >> 3;
    int lmRow = wmRow + (matid & 1) * 8 + rowin;
    int lmKp  = (matid >> 1) * 4;
    int bRow  = wnCol + (matid >> 1) * 8 + rowin;
    int bKp   = (matid & 1) * 4;

    int b = blockIdx.z;
    int n0 = blockIdx.x * 128, o0 = blockIdx.y * 128;
    const uint32_t* Bp = Bw + (size_t)b * 1024 * 256;

    uint32_t sbase = smem_u32(smp);

    auto load_tile = [&](int t, int s) {
        uint32_t as = sbase + (uint32_t)(s * STG_W) * 4u;
        uint32_t bs = as + 128u * PA * 4u;
        #pragma unroll
        for (int it = 0; it < 4; it++) {
            int idx = it * 256 + tid;
            int o = idx >> 3, ch = idx & 7;
            cp16(as + (uint32_t)(o * PA + ch * 4) * 4u,
                 A + (size_t)(o0 + o) * 256 + t * 32 + ch * 4);
        }
        #pragma unroll
        for (int it = 0; it < 4; it++) {
            int idx = it * 256 + tid;
            int r = idx >> 3, ch = idx & 7;
            cp16(bs + (uint32_t)(r * PA + ch * 4) * 4u,
                 Bp + (size_t)(n0 + r) * 256 + t * 32 + ch * 4);
        }
        CP_COMMIT();
    };

    float acc[4][4][4];
    #pragma unroll
    for (int mf = 0; mf < 4; mf++)
        #pragma unroll
        for (int nf = 0; nf < 4; nf++)
            #pragma unroll
            for (int i = 0; i < 4; i++) acc[mf][nf][i] = 0.f;

    load_tile(0, 0);
    load_tile(1, 1);

    for (int t = 0; t < 8; t++) {
        if (t < 7) { CP_WAIT(1); } else { CP_WAIT(0); }
        __syncthreads();
        if (t + 2 < 8) load_tile(t + 2, (t + 2) % 3);

        int s = t % 3;
        uint32_t aAddr = sbase + (uint32_t)(s * STG_W + lmRow * PA + lmKp) * 4u;
        uint32_t bAddr = sbase + (uint32_t)(s * STG_W + 128 * PA + bRow * PA + bKp) * 4u;

        #pragma unroll
        for (int ks = 0; ks < 4; ks++) {
            uint32_t a[4][4], bq[2][4];
            #pragma unroll
            for (int mf = 0; mf < 4; mf++)
                ldsm4(a[mf], aAddr + (uint32_t)(mf * 16 * PA + ks * 8) * 4u);
            #pragma unroll
            for (int np = 0; np < 2; np++)
                ldsm4(bq[np], bAddr + (uint32_t)(np * 16 * PA + ks * 8) * 4u);
            #pragma unroll
            for (int mf = 0; mf < 4; mf++)
                #pragma unroll
                for (int nf = 0; nf < 4; nf++)
                    mma_bf16(acc[mf][nf], a[mf], &bq[nf >> 1][(nf & 1) * 2]);
        }
    }

    if (RES) {
        #pragma unroll
        for (int mf = 0; mf < 4; mf++) {
            int r = o0 + wmRow + mf * 16 + g;
            float bi0 = bias[r], bi1 = bias[r + 8];
            size_t base0 = (size_t)b * M * N_ + (size_t)r * N_ + n0;
            size_t base1 = base0 + 8 * (size_t)N_;
            #pragma unroll
            for (int nf = 0; nf < 4; nf++) {
                int col = wnCol + nf * 8 + tg * 2;
                float2 v0 = make_float2(acc[mf][nf][0] + bi0, acc[mf][nf][1] + bi0);
                float2 v1 = make_float2(acc[mf][nf][2] + bi1, acc[mf][nf][3] + bi1);
                float2 x0 = *(const float2*)(X + base0 + col);
                float2 x1 = *(const float2*)(X + base1 + col);
                v0.x += x0.x; v0.y += x0.y;
                v1.x += x1.x; v1.y += x1.y;
                *(float2*)(OutF + base0 + col) = v0;
                *(float2*)(OutF + base1 + col) = v1;
            }
        }
    } else if (blockIdx.y >= 8) {
        // v rows: original [row][n/2] pair-along-n layout
        #pragma unroll
        for (int mf = 0; mf < 4; mf++) {
            int r = o0 + wmRow + mf * 16 + g;
            float bi0 = bias[r], bi1 = bias[r + 8];
            size_t w0 = ((size_t)b * 1536 + r) * 512;
            size_t w1 = w0 + 8 * 512;
            #pragma unroll
            for (int nf = 0; nf < 4; nf++) {
                int wc = ((n0 + wnCol + nf * 8) >> 1) + tg;
                OutW[w0 + wc] = bf2(acc[mf][nf][0] + bi0, acc[mf][nf][1] + bi0);
                OutW[w1 + wc] = bf2(acc[mf][nf][2] + bi1, acc[mf][nf][3] + bi1);
            }
        }
    } else {
        // q/k rows: transpose to [(b,h,i)][d2] pair-along-d via smem staging
        __syncthreads();               // stages free
        uint16_t* Eh = (uint16_t*)smp; // [128 n][130 bf16] = [n][65 words]
        #pragma unroll
        for (int mf = 0; mf < 4; mf++) {
            int rl = wmRow + mf * 16 + g;
            float bi0 = bias[o0 + rl], bi1 = bias[o0 + rl + 8];
            #pragma unroll
            for (int nf = 0; nf < 4; nf++) {
                int nl = wnCol + nf * 8 + tg * 2;
                Eh[nl * 130 + rl]           = bfh(acc[mf][nf][0] + bi0);
                Eh[(nl + 1) * 130 + rl]     = bfh(acc[mf][nf][1] + bi0);
                Eh[nl * 130 + rl + 8]       = bfh(acc[mf][nf][2] + bi1);
                Eh[(nl + 1) * 130 + rl + 8] = bfh(acc[mf][nf][3] + bi1);
            }
        }
        __syncthreads();
        int qk = blockIdx.y >> 2;                 // 0=q, 1=k
        uint32_t* gT = qk ? kTo : qTo;
        int h0 = (o0 - qk * 512) >> 6;            // 2 heads per tile
        #pragma unroll
        for (int it = 0; it < 32; it++) {
            int idx = it * 256 + tid;
            int i = idx >> 6, w = idx & 63;
            int h = h0 + (w >> 5);
            gT[(((size_t)b * 8 + h) * 1024 + n0 + i) * 32 + (w & 31)] =
                smp[i * 65 + w];
        }
    }
}

// ---------------------------------------------------------------------------
// bf16 mma.sync flash attention. Q/K tiles: straight cp.async from qT/kT
// ([i][d2] pair words, pitch 36) + dual-ldsm4 S-MMA (GEMM recipe). K double-
// buffered; V single-buffered with post-softmax wait (proven). 2 barriers/tile.
// ---------------------------------------------------------------------------
#define QS_W  (128 * 36)                      // 4608
#define KS_OFF QS_W                           // 2 stages of 4608
#define VS_OFF (QS_W * 3)                     // 13824
#define PS_OFF (VS_OFF + 64 * 68)             // 18176
#define ATT_SMEM ((PS_OFF + 128 * 68) * 4)    // 107,520 B
#define K8 0.18033688011112042f               // 0.125 * log2(e)

__global__ __launch_bounds__(256, 2)
void attn_tc(const uint32_t* __restrict__ qT, const uint32_t* __restrict__ kT,
             const uint32_t* __restrict__ qkvw, uint32_t* __restrict__ aow) {
    extern __shared__ uint32_t smw[];
    uint32_t* Ps = smw + PS_OFF;

    int bh = blockIdx.y;
    int b = bh >> 3, h = bh & 7;
    int i0 = blockIdx.x * 128;
    const uint32_t* qTb = qT + (size_t)(b * 8 + h) * 1024 * 32;
    const uint32_t* kTb = kT + (size_t)(b * 8 + h) * 1024 * 32;
    const uint32_t* vb  = qkvw + ((size_t)b * 1536 + 1024 + h * 64) * 512;

    int tid = threadIdx.x;
    int wid = tid >> 5, lane = tid & 31;
    int g = lane >> 2, tg = lane & 3;
    int rowin = lane & 7, matid = lane >> 3;
    int r0 = wid * 16;
    uint32_t* Psw = Ps + r0 * 68;

    uint32_t sb = smem_u32(smw);
    uint32_t qAddr  = sb + (uint32_t)(((r0 + (matid & 1) * 8 + rowin) * 36
                                      + (matid >> 1) * 4) * 4);
    uint32_t kFrag  = (uint32_t)((((matid >> 1) * 8 + rowin) * 36
                                  + (matid & 1) * 4) * 4);
    uint32_t vsBase = sb + (uint32_t)(VS_OFF * 4)
        + (uint32_t)((((matid >> 1) * 8 + rowin) * 68 + (matid & 1) * 4) * 4);

    // prologue: Q tile + K tile 0 (stage 0)
    #pragma unroll
    for (int it = 0; it < 4; it++) {
        int idx = it * 256 + tid;
        int row = idx >> 3, ch = idx & 7;
        cp16(sb + (uint32_t)((row * 36 + ch * 4) * 4),
             qTb + (size_t)(i0 + row) * 32 + ch * 4);
        cp16(sb + (uint32_t)((KS_OFF + row * 36 + ch * 4) * 4),
             kTb + (size_t)row * 32 + ch * 4);
    }
    CP_COMMIT();
    CP_WAIT(0);
    __syncthreads();

    float m0 = -1e30f, m1 = -1e30f, l0 = 0.f, l1 = 0.f;
    float o_acc[8][4];
    #pragma unroll
    for (int nf = 0; nf < 8; nf++)
        #pragma unroll
        for (int i = 0; i < 4; i++) o_acc[nf][i] = 0.f;

    int cpD = tid >> 2, cpC = tid & 3;

    for (int t = 0; t < 8; t++) {
        int j0 = t * 128;
        if (t) __syncthreads();       // all warps done with Vs (PV t-1)

        // issue V(t); prefetch K(t+1) into the other stage
        #pragma unroll
        for (int it = 0; it < 4; it++)
            cp16(sb + (uint32_t)((VS_OFF + cpD * 68 + cpC * 4 + it * 16) * 4),
                 vb + (size_t)cpD * 512 + (j0 >> 1) + cpC * 4 + it * 16);
        if (t < 7) {
            uint32_t ksDst = sb + (uint32_t)((KS_OFF + ((t + 1) & 1) * QS_W) * 4);
            #pragma unroll
            for (int it = 0; it < 4; it++) {
                int idx = it * 256 + tid;
                int row = idx >> 3, ch = idx & 7;
                cp16(ksDst + (uint32_t)((row * 36 + ch * 4) * 4),
                     kTb + (size_t)(j0 + 128 + row) * 32 + ch * 4);
            }
        }
        CP_COMMIT();

        // S = Q K^T (dual ldsm4, GEMM recipe)
        uint32_t ksCur = sb + (uint32_t)((KS_OFF + (t & 1) * QS_W) * 4) + kFrag;
        float acc[16][4];
        #pragma unroll
        for (int nf = 0; nf < 16; nf++)
            #pragma unroll
            for (int i = 0; i < 4; i++) acc[nf][i] = 0.f;

        #pragma unroll
        for (int ks = 0; ks < 4; ks++) {
            uint32_t a[4];
            ldsm4(a, qAddr + (uint32_t)(ks * 8 * 4));
            #pragma unroll
            for (int nb = 0; nb < 8; nb++) {
                uint32_t bq[4];
                ldsm4(bq, ksCur + (uint32_t)((nb * 16 * 36 + ks * 8) * 4));
                mma_bf16(acc[nb * 2],     a, &bq[0]);
                mma_bf16(acc[nb * 2 + 1], a, &bq[2]);
            }
        }

        // online softmax (1/8 scale folded into exp2 constant)
        float rm0 = -1e30f, rm1 = -1e30f;
        #pragma unroll
        for (int nf = 0; nf < 16; nf++) {
            rm0 = fmaxf(rm0, fmaxf(acc[nf][0], acc[nf][1]));
            rm1 = fmaxf(rm1, fmaxf(acc[nf][2], acc[nf][3]));
        }
        rm0 = fmaxf(rm0, __shfl_xor_sync(0xffffffffu, rm0, 1));
        rm0 = fmaxf(rm0, __shfl_xor_sync(0xffffffffu, rm0, 2));
        rm1 = fmaxf(rm1, __shfl_xor_sync(0xffffffffu, rm1, 1));
        rm1 = fmaxf(rm1, __shfl_xor_sync(0xffffffffu, rm1, 2));
        float mn0 = fmaxf(m0, rm0), mn1 = fmaxf(m1, rm1);
        float c0 = ex2((m0 - mn0) * K8), c1 = ex2((m1 - mn1) * K8);
        l0 *= c0; l1 *= c1;
        #pragma unroll
        for (int nf = 0; nf < 8; nf++) {
            o_acc[nf][0] *= c0; o_acc[nf][1] *= c0;
            o_acc[nf][2] *= c1; o_acc[nf][3] *= c1;
        }
        float s0 = 0.f, s1 = 0.f;
        #pragma unroll
        for (int nf = 0; nf < 16; nf++) {
            float p0 = ex2((acc[nf][0] - mn0) * K8);
            float p1 = ex2((acc[nf][1] - mn0) * K8);
            float p2 = ex2((acc[nf][2] - mn1) * K8);
            float p3 = ex2((acc[nf][3] - mn1) * K8);
            s0 += p0 + p1; s1 += p2 + p3;
            Psw[g * 68 + nf * 4 + tg]       = bf2(p0, p1);
            Psw[(g + 8) * 68 + nf * 4 + tg] = bf2(p2, p3);
        }
        s0 += __shfl_xor_sync(0xffffffffu, s0, 1);
        s0 += __shfl_xor_sync(0xffffffffu, s0, 2);
        s1 += __shfl_xor_sync(0xffffffffu, s1, 1);
        s1 += __shfl_xor_sync(0xffffffffu, s1, 2);
        l0 += s0; l1 += s1; m0 = mn0; m1 = mn1;

        CP_WAIT(0);
        __syncthreads();   // V(t) and K(t+1) visible; Psw visible in-warp

        // O += P @ V^T
        #pragma unroll
        for (int kk = 0; kk < 8; kk++) {
            int jp = kk * 8;
            uint32_t a[4];
            a[0] = Psw[g * 68 + jp + tg];
            a[1] = Psw[(g + 8) * 68 + jp + tg];
            a[2] = Psw[g * 68 + jp + tg + 4];
            a[3] = Psw[(g + 8) * 68 + jp + tg + 4];
            uint32_t bq[4][4];
            #pragma unroll
            for (int q = 0; q < 4; q++)
                ldsm4(bq[q], vsBase + (uint32_t)((q * 16 * 68 + jp) * 4));
            #pragma unroll
            for (int nf = 0; nf < 8; nf++)
                mma_bf16(o_acc[nf], a, &bq[nf >> 1][(nf & 1) * 2]);
        }
    }

    // epilogue: normalize -> Os[128 i][33] (reuse Ps) -> coalesced k-major store
    __syncthreads();
    float inv0 = 1.f / l0, inv1 = 1.f / l1;
    uint32_t* Os = Ps;
    #pragma unroll
    for (int nf = 0; nf < 8; nf++) {
        int d2 = nf * 4 + tg;
        Os[(r0 + g) * 33 + d2]     = bf2(o_acc[nf][0] * inv0, o_acc[nf][1] * inv0);
        Os[(r0 + g + 8) * 33 + d2] = bf2(o_acc[nf][2] * inv1, o_acc[nf][3] * inv1);
    }
    __syncthreads();
    uint32_t* aob = aow + (size_t)b * 1024 * 256 + h * 32;
    #pragma unroll
    for (int it = 0; it < 16; it++) {
        int idx = it * 256 + tid;
        int i = idx >> 5, c2 = idx & 31;
        aob[(size_t)(i0 + i) * 256 + c2] = Os[i * 33 + c2];
    }
}

// ---------------------------------------------------------------------------
extern "C" void kernel_launch(void* const* d_in, const int* in_sizes, int n_in,
                              void* d_out, int out_size) {
    const float* x      = (const float*)d_in[0];
    const float* gn_w   = (const float*)d_in[1];
    const float* gn_b   = (const float*)d_in[2];
    const float* qkv_w  = (const float*)d_in[3];
    const float* qkv_b  = (const float*)d_in[4];
    const float* proj_w = (const float*)d_in[5];
    const float* proj_b = (const float*)d_in[6];
    float* out = (float*)d_out;

    uint32_t *hbuf, *qkvbuf, *aobuf, *wq, *wp, *qTbuf, *kTbuf;
    cudaGetSymbolAddress((void**)&hbuf,   g_h);
    cudaGetSymbolAddress((void**)&qkvbuf, g_qkvw);
    cudaGetSymbolAddress((void**)&aobuf,  g_aow);
    cudaGetSymbolAddress((void**)&wq,     g_wq);
    cudaGetSymbolAddress((void**)&wp,     g_wp);
    cudaGetSymbolAddress((void**)&qTbuf,  g_qT);
    cudaGetSymbolAddress((void**)&kTbuf,  g_kT);

    cudaFuncSetAttribute(attn_tc, cudaFuncAttributeMaxDynamicSharedMemorySize, ATT_SMEM);
    cudaFuncSetAttribute(tc_gemm<false>, cudaFuncAttributeMaxDynamicSharedMemorySize, GM_SMEM);
    cudaFuncSetAttribute(tc_gemm<true>,  cudaFuncAttributeMaxDynamicSharedMemorySize, GM_SMEM);

    // 0) weight conversion (both, one launch)
    wconv2<<<(WQ4 + WP4 + 255) / 256, 256>>>((const float4*)qkv_w, (const float4*)proj_w,
                                             (uint2*)wq, (uint2*)wp);
    // 1) GroupNorm -> k-major bf16 pair words
    gn_kernel<<<B_ * GROUPS, 256>>>(x, gn_w, gn_b);
    // 2) QKV GEMM: q/k -> transposed [i][d2]; v -> [row][n/2]
    tc_gemm<false><<<dim3(8, 12, B_), 256, GM_SMEM>>>(wq, qkv_b, hbuf, nullptr,
                                                      nullptr, qkvbuf, qTbuf, kTbuf, 1536);
    // 3) Flash attention (dual-ldsm4 S-MMA, async Q/K/V)
    attn_tc<<<dim3(8, B_ * HEADS), 256, ATT_SMEM>>>(qTbuf, kTbuf, qkvbuf, aobuf);
    // 4) Proj GEMM + bias + residual -> fp32 out
    tc_gemm<true><<<dim3(8, 4, B_), 256, GM_SMEM>>>(wp, proj_b, aobuf, x,
                                                    out, nullptr, nullptr, nullptr, 512);
}